// round 3
// baseline (speedup 1.0000x reference)
#include <cuda_runtime.h>

// ---------------------------------------------------------------------------
// MSDeformableAttention, fp32 SIMT baseline.
//   B=2, NQ=10000, C=256, M=8 heads, L=3 levels, K=4 points, D=32
//   levels: 100x100, 50x50, 25x25  (HW = 10000, 2500, 625; total 13125)
//
// Pipeline:
//   1. gemm_colA : per (b,level) value projection  proj[p, o] = sum_c V[c,p] Wv[o,c] + bv
//                  stored pixel-major: g_proj[(b*13125 + loff + p)*256 + o]
//   2. gemm_rowA : sampling offsets  S = Q @ Ws^T + bs   (20000 x 192)
//   3. gemm_rowA : attn logits       A = Q @ Wa^T + ba   (20000 x 96)
//   4. softmax12 : softmax over the 12 (L*K) logits per (q, head), in place
//   5. sample_kernel : bilinear gather + weighted sum -> g_mid (20000 x 256)
//   6. gemm_rowA : out = g_mid @ Wo^T + bo -> d_out
// ---------------------------------------------------------------------------

#define B_    2
#define NQ_   10000
#define C_    256
#define M_    8
#define L_    3
#define KP_   4
#define D_    32
#define HW0   10000
#define HW1   2500
#define HW2   625
#define HWTOT 13125
#define NR_   (B_ * NQ_)      // 20000 query rows

// Scratch (device globals; no dynamic allocation allowed)
__device__ float g_proj[(size_t)B_ * HWTOT * C_];   // 26.9 MB
__device__ float g_offs[(size_t)NR_ * 192];
__device__ float g_attn[(size_t)NR_ * 96];
__device__ float g_mid [(size_t)NR_ * C_];

// ------------------------------- GEMM tiles --------------------------------
#define BM 128
#define BN 64
#define BK 16
// 256 threads: 16x16 logical grid, each thread computes 8x4 outputs.

// Y[N,O] = X[N,C_] @ W[O,C_]^T + bias,  X row-major, Y row-major (ld = O)
__global__ __launch_bounds__(256) void gemm_rowA(
    const float* __restrict__ X, const float* __restrict__ W,
    const float* __restrict__ bias, float* __restrict__ Y,
    int N, int O)
{
    __shared__ float As[BK][BM];
    __shared__ float Bs[BK][BN];

    const int t   = threadIdx.x;
    const int tx  = t & 15;      // 0..15 -> 4 cols each
    const int ty  = t >> 4;      // 0..15 -> 8 rows each
    const int row0 = blockIdx.x * BM;
    const int col0 = blockIdx.y * BN;

    float acc[8][4];
#pragma unroll
    for (int i = 0; i < 8; i++)
#pragma unroll
        for (int j = 0; j < 4; j++) acc[i][j] = 0.f;

    // A-load mapping: 128 rows x 16 k = 2048 floats, 8 per thread (two float4)
    const int aRow = t >> 1;            // 0..127
    const int aK   = (t & 1) * 8;       // 0 or 8
    const int aRowG = row0 + aRow;
    // B-load mapping: 64 o x 16 k = 1024 floats, 4 per thread (one float4)
    const int bO = t >> 2;              // 0..63
    const int bK = (t & 3) * 4;         // 0,4,8,12
    const int bOG = col0 + bO;

    for (int k0 = 0; k0 < C_; k0 += BK) {
        if (aRowG < N) {
            const float4* src = reinterpret_cast<const float4*>(
                X + (size_t)aRowG * C_ + k0 + aK);
            float4 v0 = src[0], v1 = src[1];
            As[aK + 0][aRow] = v0.x; As[aK + 1][aRow] = v0.y;
            As[aK + 2][aRow] = v0.z; As[aK + 3][aRow] = v0.w;
            As[aK + 4][aRow] = v1.x; As[aK + 5][aRow] = v1.y;
            As[aK + 6][aRow] = v1.z; As[aK + 7][aRow] = v1.w;
        } else {
#pragma unroll
            for (int j = 0; j < 8; j++) As[aK + j][aRow] = 0.f;
        }
        if (bOG < O) {
            float4 w4 = *reinterpret_cast<const float4*>(
                W + (size_t)bOG * C_ + k0 + bK);
            Bs[bK + 0][bO] = w4.x; Bs[bK + 1][bO] = w4.y;
            Bs[bK + 2][bO] = w4.z; Bs[bK + 3][bO] = w4.w;
        } else {
#pragma unroll
            for (int j = 0; j < 4; j++) Bs[bK + j][bO] = 0.f;
        }
        __syncthreads();

#pragma unroll
        for (int kk = 0; kk < BK; kk++) {
            float4 a0 = *reinterpret_cast<const float4*>(&As[kk][ty * 8]);
            float4 a1 = *reinterpret_cast<const float4*>(&As[kk][ty * 8 + 4]);
            float4 b0 = *reinterpret_cast<const float4*>(&Bs[kk][tx * 4]);
            float a[8] = {a0.x, a0.y, a0.z, a0.w, a1.x, a1.y, a1.z, a1.w};
            float b[4] = {b0.x, b0.y, b0.z, b0.w};
#pragma unroll
            for (int i = 0; i < 8; i++)
#pragma unroll
                for (int j = 0; j < 4; j++)
                    acc[i][j] = fmaf(a[i], b[j], acc[i][j]);
        }
        __syncthreads();
    }

#pragma unroll
    for (int i = 0; i < 8; i++) {
        int r = row0 + ty * 8 + i;
        if (r >= N) continue;
#pragma unroll
        for (int j = 0; j < 4; j++) {
            int o = col0 + tx * 4 + j;
            if (o < O) Y[(size_t)r * O + o] = acc[i][j] + bias[o];
        }
    }
}

// Y[p, o] = sum_c A[c*HW + p] * W[o*C_ + c] + bias[o]
// A is (C_, HW) channel-major (one batch of one level). Y stride = 256.
__global__ __launch_bounds__(256) void gemm_colA(
    const float* __restrict__ A, const float* __restrict__ W,
    const float* __restrict__ bias, float* __restrict__ Y, int HW)
{
    __shared__ float As[BK][BM];
    __shared__ float Bs[BK][BN];

    const int t  = threadIdx.x;
    const int tx = t & 15;
    const int ty = t >> 4;
    const int p0   = blockIdx.x * BM;
    const int col0 = blockIdx.y * BN;

    float acc[8][4];
#pragma unroll
    for (int i = 0; i < 8; i++)
#pragma unroll
        for (int j = 0; j < 4; j++) acc[i][j] = 0.f;

    // A-load: kk = t>>4 (0..15), pixel i = (t&15)*8 .. +7 (contiguous in gmem)
    const int aKK = t >> 4;
    const int aI  = (t & 15) * 8;
    const int bO = t >> 2;
    const int bK = (t & 3) * 4;
    const int bOG = col0 + bO;

    for (int k0 = 0; k0 < C_; k0 += BK) {
        const float* arow = A + (size_t)(k0 + aKK) * HW;
#pragma unroll
        for (int j = 0; j < 8; j++) {
            int p = p0 + aI + j;
            As[aKK][aI + j] = (p < HW) ? arow[p] : 0.f;
        }
        {
            float4 w4 = *reinterpret_cast<const float4*>(
                W + (size_t)bOG * C_ + k0 + bK);
            Bs[bK + 0][bO] = w4.x; Bs[bK + 1][bO] = w4.y;
            Bs[bK + 2][bO] = w4.z; Bs[bK + 3][bO] = w4.w;
        }
        __syncthreads();

#pragma unroll
        for (int kk = 0; kk < BK; kk++) {
            float4 a0 = *reinterpret_cast<const float4*>(&As[kk][ty * 8]);
            float4 a1 = *reinterpret_cast<const float4*>(&As[kk][ty * 8 + 4]);
            float4 b0 = *reinterpret_cast<const float4*>(&Bs[kk][tx * 4]);
            float a[8] = {a0.x, a0.y, a0.z, a0.w, a1.x, a1.y, a1.z, a1.w};
            float b[4] = {b0.x, b0.y, b0.z, b0.w};
#pragma unroll
            for (int i = 0; i < 8; i++)
#pragma unroll
                for (int j = 0; j < 4; j++)
                    acc[i][j] = fmaf(a[i], b[j], acc[i][j]);
        }
        __syncthreads();
    }

#pragma unroll
    for (int i = 0; i < 8; i++) {
        int p = p0 + ty * 8 + i;
        if (p >= HW) continue;
#pragma unroll
        for (int j = 0; j < 4; j++) {
            int o = col0 + tx * 4 + j;
            Y[(size_t)p * C_ + o] = acc[i][j] + bias[o];
        }
    }
}

// -------------------------- softmax over 12 logits -------------------------
__global__ __launch_bounds__(256) void softmax12(float* __restrict__ attn)
{
    int g = blockIdx.x * 256 + threadIdx.x;      // group = bq * 8 + m
    if (g >= NR_ * M_) return;
    float* p = attn + (size_t)g * 12;
    float v[12];
    float mx = -1e30f;
#pragma unroll
    for (int i = 0; i < 12; i++) { v[i] = p[i]; mx = fmaxf(mx, v[i]); }
    float s = 0.f;
#pragma unroll
    for (int i = 0; i < 12; i++) { v[i] = __expf(v[i] - mx); s += v[i]; }
    float inv = 1.f / s;
#pragma unroll
    for (int i = 0; i < 12; i++) p[i] = v[i] * inv;
}

// ------------------- bilinear sampling + weighted aggregation --------------
// grid = B*NQ blocks, 256 threads = 8 warps; warp = head m, lane = channel d.
__global__ __launch_bounds__(256) void sample_kernel(
    const float* __restrict__ ref, float* __restrict__ mid)
{
    const int bq   = blockIdx.x;
    const int b    = bq / NQ_;
    const int warp = threadIdx.x >> 5;   // head m
    const int lane = threadIdx.x & 31;   // channel d

    const float rx = __ldg(&ref[2 * bq + 0]);
    const float ry = __ldg(&ref[2 * bq + 1]);

    const float* off_row  = g_offs + (size_t)bq * 192 + warp * 24;  // (L,K,2)
    const float* attn_row = g_attn + (size_t)bq * 96 + warp * 12;   // (L*K)

    const int Hs[3]    = {100, 50, 25};
    const int Ws_[3]   = {100, 50, 25};
    const int loffs[3] = {0, HW0, HW0 + HW1};

    float acc = 0.f;
#pragma unroll
    for (int l = 0; l < L_; l++) {
        const int   Hh = Hs[l], Ww = Ws_[l];
        const float* projb =
            g_proj + ((size_t)b * HWTOT + loffs[l]) * C_ + warp * D_ + lane;
#pragma unroll
        for (int k = 0; k < KP_; k++) {
            float ox = off_row[l * 8 + k * 2 + 0];
            float oy = off_row[l * 8 + k * 2 + 1];
            float aw = attn_row[l * 4 + k];

            float px = fmaf(rx, (float)Ww, ox) - 0.5f;
            float py = fmaf(ry, (float)Hh, oy) - 0.5f;
            float x0f = floorf(px), y0f = floorf(py);
            int x0 = (int)x0f, y0 = (int)y0f;
            float wx1 = px - x0f, wy1 = py - y0f;
            float wx0 = 1.f - wx1, wy0 = 1.f - wy1;

            bool vx0 = (x0 >= 0) && (x0 < Ww);
            bool vx1 = (x0 + 1 >= 0) && (x0 + 1 < Ww);
            bool vy0 = (y0 >= 0) && (y0 < Hh);
            bool vy1 = (y0 + 1 >= 0) && (y0 + 1 < Hh);

            float s = 0.f;
            if (vy0) {
                const float* rowp = projb + (size_t)y0 * Ww * C_;
                if (vx0) s = fmaf(wx0 * wy0, rowp[(size_t)x0 * C_], s);
                if (vx1) s = fmaf(wx1 * wy0, rowp[(size_t)(x0 + 1) * C_], s);
            }
            if (vy1) {
                const float* rowp = projb + (size_t)(y0 + 1) * Ww * C_;
                if (vx0) s = fmaf(wx0 * wy1, rowp[(size_t)x0 * C_], s);
                if (vx1) s = fmaf(wx1 * wy1, rowp[(size_t)(x0 + 1) * C_], s);
            }
            acc = fmaf(aw, s, acc);
        }
    }
    mid[(size_t)bq * C_ + warp * D_ + lane] = acc;
}

// --------------------------------- launch ----------------------------------
extern "C" void kernel_launch(void* const* d_in, const int* in_sizes, int n_in,
                              void* d_out, int out_size)
{
    const float* query = (const float*)d_in[0];
    const float* refp  = (const float*)d_in[1];
    const float* vals[3] = {(const float*)d_in[2], (const float*)d_in[3],
                            (const float*)d_in[4]};
    const float* Wv    = (const float*)d_in[5];
    const float* bv    = (const float*)d_in[6];
    const float* Wsmp  = (const float*)d_in[7];
    const float* bsmp  = (const float*)d_in[8];
    const float* Wa    = (const float*)d_in[9];
    const float* ba    = (const float*)d_in[10];
    const float* Wo    = (const float*)d_in[11];
    const float* bo    = (const float*)d_in[12];
    float* out = (float*)d_out;

    float *proj, *offs, *attn, *mid;
    cudaGetSymbolAddress((void**)&proj, g_proj);
    cudaGetSymbolAddress((void**)&offs, g_offs);
    cudaGetSymbolAddress((void**)&attn, g_attn);
    cudaGetSymbolAddress((void**)&mid,  g_mid);

    const int HWs[3]   = {HW0, HW1, HW2};
    const int loffs[3] = {0, HW0, HW0 + HW1};

    // 1) value projection per (batch, level)
    for (int b = 0; b < B_; b++) {
        for (int l = 0; l < L_; l++) {
            int hw = HWs[l];
            dim3 grid((hw + BM - 1) / BM, C_ / BN);
            gemm_colA<<<grid, 256>>>(
                vals[l] + (size_t)b * C_ * hw, Wv, bv,
                proj + ((size_t)b * HWTOT + loffs[l]) * C_, hw);
        }
    }

    // 2) offsets + 3) attn logits
    {
        dim3 g1((NR_ + BM - 1) / BM, (192 + BN - 1) / BN);
        gemm_rowA<<<g1, 256>>>(query, Wsmp, bsmp, offs, NR_, 192);
        dim3 g2((NR_ + BM - 1) / BM, (96 + BN - 1) / BN);
        gemm_rowA<<<g2, 256>>>(query, Wa, ba, attn, NR_, 96);
    }

    // 4) softmax over L*K per (q, head)
    softmax12<<<(NR_ * M_ + 255) / 256, 256>>>(attn);

    // 5) bilinear sampling + aggregation
    sample_kernel<<<NR_, 256>>>(refp, mid);

    // 6) output projection
    {
        dim3 g3((NR_ + BM - 1) / BM, (C_ + BN - 1) / BN);
        gemm_rowA<<<g3, 256>>>(mid, Wo, bo, out, NR_, C_);
    }
}

// round 7
// speedup vs baseline: 1.3332x; 1.3332x over previous
#include <cuda_runtime.h>

// ---------------------------------------------------------------------------
// MSDeformableAttention — round 5: round-3 design with the gemm_v alignment
// bug fixed (level 2 has HW=625, odd, so A-row float4 loads were misaligned).
//   B=2, NQ=10000, C=256, M=8, L=3, K=4, D=32; levels 100x100/50x50/25x25
//
// Pipeline:
//   1. gemm_v : fused value projection, all (b, level) in one launch,
//               output pixel-major g_proj[(b*13125+loff+p)*256 + o]
//   2. gemm_q : fused offsets+attn GEMM (20000 x 288) -> g_sa
//   3. sample_kernel : per-(b,q) softmax (warp shuffle) + bilinear gather
//   4. gemm_q : output projection (20000 x 256) -> d_out
// ---------------------------------------------------------------------------

#define B_    2
#define NQ_   10000
#define C_    256
#define M_    8
#define L_    3
#define KP_   4
#define D_    32
#define HW0   10000
#define HW1   2500
#define HW2   625
#define HWTOT 13125
#define NR_   (B_ * NQ_)     // 20000
#define SA_W  288            // 192 offsets + 96 attn logits per row

__device__ float g_proj[(size_t)B_ * HWTOT * C_];   // 26.9 MB, pixel-major
__device__ float g_sa  [(size_t)NR_ * SA_W];        // 23.0 MB
__device__ float g_mid [(size_t)NR_ * C_];          // 20.5 MB

#define BM 128
#define BN 128
#define BK 8
#define NIT (C_ / BK)        // 32

// ------------------------- generic query-side GEMM -------------------------
// Y[N, Otot] = X[N, C_] @ [W1;W2]^T + [b1;b2]
// column o < O1 uses W1 row o; otherwise W2 row (o-O1). Otot may be ragged.
__global__ __launch_bounds__(256) void gemm_q(
    const float* __restrict__ X, int N,
    const float* __restrict__ W1, const float* __restrict__ bias1, int O1,
    const float* __restrict__ W2, const float* __restrict__ bias2, int Otot,
    float* __restrict__ Y)
{
    __shared__ float As[2][BK][BM];
    __shared__ float Bs[2][BK][BN];

    const int t    = threadIdx.x;
    const int row0 = blockIdx.x * BM;
    const int col0 = blockIdx.y * BN;

    // loader mapping: 128 lanes x 2 k-quads
    const int lr = t & 127;
    const int lk = (t >> 7) * 4;
    const int aRowG = row0 + lr;
    const int oG    = col0 + lr;
    const bool aOk  = aRowG < N;
    const bool bOk  = oG < Otot;
    const float* __restrict__ xrow = X + (size_t)(aOk ? aRowG : 0) * C_;
    const float* __restrict__ wrow =
        bOk ? ((oG < O1) ? W1 + (size_t)oG * C_
                         : W2 + (size_t)(oG - O1) * C_)
            : W1;

    // compute mapping: 16x16 threads, 8x8 outputs (B split tx*4 / 64+tx*4)
    const int tx = t & 15;
    const int ty = t >> 4;

    float acc[8][8];
#pragma unroll
    for (int i = 0; i < 8; i++)
#pragma unroll
        for (int j = 0; j < 8; j++) acc[i][j] = 0.f;

    float4 aR, bR;
    aR = aOk ? *(const float4*)(xrow + lk) : make_float4(0, 0, 0, 0);
    bR = bOk ? *(const float4*)(wrow + lk) : make_float4(0, 0, 0, 0);
    As[0][lk + 0][lr] = aR.x; As[0][lk + 1][lr] = aR.y;
    As[0][lk + 2][lr] = aR.z; As[0][lk + 3][lr] = aR.w;
    Bs[0][lk + 0][lr] = bR.x; Bs[0][lk + 1][lr] = bR.y;
    Bs[0][lk + 2][lr] = bR.z; Bs[0][lk + 3][lr] = bR.w;
    __syncthreads();

    for (int it = 0; it < NIT; ++it) {
        const int cb = it & 1;
        if (it + 1 < NIT) {
            const int k0 = (it + 1) * BK + lk;
            aR = aOk ? *(const float4*)(xrow + k0) : make_float4(0, 0, 0, 0);
            bR = bOk ? *(const float4*)(wrow + k0) : make_float4(0, 0, 0, 0);
        }
#pragma unroll
        for (int kk = 0; kk < BK; ++kk) {
            float4 a0 = *(const float4*)&As[cb][kk][ty * 8];
            float4 a1 = *(const float4*)&As[cb][kk][ty * 8 + 4];
            float4 b0 = *(const float4*)&Bs[cb][kk][tx * 4];
            float4 b1 = *(const float4*)&Bs[cb][kk][64 + tx * 4];
            float a[8] = {a0.x, a0.y, a0.z, a0.w, a1.x, a1.y, a1.z, a1.w};
            float b[8] = {b0.x, b0.y, b0.z, b0.w, b1.x, b1.y, b1.z, b1.w};
#pragma unroll
            for (int i = 0; i < 8; i++)
#pragma unroll
                for (int j = 0; j < 8; j++)
                    acc[i][j] = fmaf(a[i], b[j], acc[i][j]);
        }
        if (it + 1 < NIT) {
            const int nb = cb ^ 1;
            As[nb][lk + 0][lr] = aR.x; As[nb][lk + 1][lr] = aR.y;
            As[nb][lk + 2][lr] = aR.z; As[nb][lk + 3][lr] = aR.w;
            Bs[nb][lk + 0][lr] = bR.x; Bs[nb][lk + 1][lr] = bR.y;
            Bs[nb][lk + 2][lr] = bR.z; Bs[nb][lk + 3][lr] = bR.w;
        }
        __syncthreads();
    }

    // epilogue
    int   ocol[8];
    float bcol[8];
#pragma unroll
    for (int j = 0; j < 8; j++) {
        const int o = col0 + tx * 4 + ((j < 4) ? j : 60 + j);  // 2nd half +64
        ocol[j] = o;
        bcol[j] = (o < Otot) ? ((o < O1) ? bias1[o] : bias2[o - O1]) : 0.f;
    }
#pragma unroll
    for (int i = 0; i < 8; i++) {
        const int r = row0 + ty * 8 + i;
        if (r >= N) continue;
        float* yr = Y + (size_t)r * Otot;
        if (ocol[3] < Otot) {
            float4 v = make_float4(acc[i][0] + bcol[0], acc[i][1] + bcol[1],
                                   acc[i][2] + bcol[2], acc[i][3] + bcol[3]);
            *(float4*)(yr + ocol[0]) = v;
        } else {
#pragma unroll
            for (int j = 0; j < 4; j++)
                if (ocol[j] < Otot) yr[ocol[j]] = acc[i][j] + bcol[j];
        }
        if (ocol[7] < Otot) {
            float4 v = make_float4(acc[i][4] + bcol[4], acc[i][5] + bcol[5],
                                   acc[i][6] + bcol[6], acc[i][7] + bcol[7]);
            *(float4*)(yr + ocol[4]) = v;
        } else {
#pragma unroll
            for (int j = 4; j < 8; j++)
                if (ocol[j] < Otot) yr[ocol[j]] = acc[i][j] + bcol[j];
        }
    }
}

// --------------------- fused value projection (all b,l) ---------------------
// proj[(b*HWTOT + loff + p)*256 + o] = sum_c V[b][c][p] * Wv[o][c] + bv[o]
// blockIdx.x encodes (b, level, pixel-tile): 79 + 20 + 5 tiles per batch.
__global__ __launch_bounds__(256) void gemm_v(
    const float* __restrict__ V0, const float* __restrict__ V1,
    const float* __restrict__ V2, const float* __restrict__ Wv,
    const float* __restrict__ bv)
{
    __shared__ float As[2][BK][BM];
    __shared__ float Bs[2][BK][BN];

    const int t  = threadIdx.x;
    const int bx = blockIdx.x;
    const int b  = bx / 104;
    const int tl = bx - b * 104;
    int p0, HW, loff;
    const float* A;
    if (tl < 79)      { p0 = tl * 128;        HW = HW0; loff = 0;         A = V0; }
    else if (tl < 99) { p0 = (tl - 79) * 128; HW = HW1; loff = HW0;       A = V1; }
    else              { p0 = (tl - 99) * 128; HW = HW2; loff = HW0 + HW1; A = V2; }
    A += (size_t)b * C_ * HW;
    const int col0 = blockIdx.y * BN;

    // A loader: kA = t>>5 (0..7 k rows), pI = (t&31)*4 contiguous pixels
    const int pI = (t & 31) * 4;
    const int kA = t >> 5;
    // B loader: 128 lanes x 2 k-quads
    const int lr = t & 127;
    const int lk = (t >> 7) * 4;
    const float* __restrict__ wrow = Wv + (size_t)(col0 + lr) * C_;

    const int tx = t & 15;
    const int ty = t >> 4;

    float acc[8][8];
#pragma unroll
    for (int i = 0; i < 8; i++)
#pragma unroll
        for (int j = 0; j < 8; j++) acc[i][j] = 0.f;

    const bool pFull = (p0 + pI + 3) < HW;
    // float4 A-path is legal only when every row base stays 16B aligned:
    // row stride HW must be a multiple of 4 floats (fails for level 2, HW=625)
    const bool vec4 = pFull && ((HW & 3) == 0);

    float4 aR, bR;
    {
        const float* src = A + (size_t)kA * HW + p0 + pI;
        if (vec4) aR = *(const float4*)src;
        else {
            aR.x = (p0 + pI + 0 < HW) ? src[0] : 0.f;
            aR.y = (p0 + pI + 1 < HW) ? src[1] : 0.f;
            aR.z = (p0 + pI + 2 < HW) ? src[2] : 0.f;
            aR.w = (p0 + pI + 3 < HW) ? src[3] : 0.f;
        }
        bR = *(const float4*)(wrow + lk);
    }
    *(float4*)&As[0][kA][pI] = aR;
    Bs[0][lk + 0][lr] = bR.x; Bs[0][lk + 1][lr] = bR.y;
    Bs[0][lk + 2][lr] = bR.z; Bs[0][lk + 3][lr] = bR.w;
    __syncthreads();

    for (int it = 0; it < NIT; ++it) {
        const int cb = it & 1;
        if (it + 1 < NIT) {
            const int kbase = (it + 1) * BK;
            const float* src = A + (size_t)(kbase + kA) * HW + p0 + pI;
            if (vec4) aR = *(const float4*)src;
            else {
                aR.x = (p0 + pI + 0 < HW) ? src[0] : 0.f;
                aR.y = (p0 + pI + 1 < HW) ? src[1] : 0.f;
                aR.z = (p0 + pI + 2 < HW) ? src[2] : 0.f;
                aR.w = (p0 + pI + 3 < HW) ? src[3] : 0.f;
            }
            bR = *(const float4*)(wrow + kbase + lk);
        }
#pragma unroll
        for (int kk = 0; kk < BK; ++kk) {
            float4 a0 = *(const float4*)&As[cb][kk][ty * 8];
            float4 a1 = *(const float4*)&As[cb][kk][ty * 8 + 4];
            float4 b0 = *(const float4*)&Bs[cb][kk][tx * 4];
            float4 b1 = *(const float4*)&Bs[cb][kk][64 + tx * 4];
            float a[8] = {a0.x, a0.y, a0.z, a0.w, a1.x, a1.y, a1.z, a1.w};
            float b[8] = {b0.x, b0.y, b0.z, b0.w, b1.x, b1.y, b1.z, b1.w};
#pragma unroll
            for (int i = 0; i < 8; i++)
#pragma unroll
                for (int j = 0; j < 8; j++)
                    acc[i][j] = fmaf(a[i], b[j], acc[i][j]);
        }
        if (it + 1 < NIT) {
            const int nb = cb ^ 1;
            *(float4*)&As[nb][kA][pI] = aR;
            Bs[nb][lk + 0][lr] = bR.x; Bs[nb][lk + 1][lr] = bR.y;
            Bs[nb][lk + 2][lr] = bR.z; Bs[nb][lk + 3][lr] = bR.w;
        }
        __syncthreads();
    }

    // epilogue: pixels are rows, channels are cols (O=256 always in range)
    float bcol[8];
#pragma unroll
    for (int j = 0; j < 8; j++)
        bcol[j] = bv[col0 + tx * 4 + ((j < 4) ? j : 60 + j)];
#pragma unroll
    for (int i = 0; i < 8; i++) {
        const int p = p0 + ty * 8 + i;
        if (p >= HW) continue;
        float* yr = g_proj + (size_t)(b * HWTOT + loff + p) * C_ + col0;
        *(float4*)(yr + tx * 4) =
            make_float4(acc[i][0] + bcol[0], acc[i][1] + bcol[1],
                        acc[i][2] + bcol[2], acc[i][3] + bcol[3]);
        *(float4*)(yr + 64 + tx * 4) =
            make_float4(acc[i][4] + bcol[4], acc[i][5] + bcol[5],
                        acc[i][6] + bcol[6], acc[i][7] + bcol[7]);
    }
}

// ------------- bilinear sampling + aggregation, softmax fused ---------------
// grid = B*NQ blocks, 8 warps (= heads), lane = channel d.
__global__ __launch_bounds__(256) void sample_kernel(
    const float* __restrict__ ref, float* __restrict__ mid)
{
    const int bq   = blockIdx.x;
    const int b    = bq / NQ_;
    const int warp = threadIdx.x >> 5;
    const int lane = threadIdx.x & 31;

    const float2 r2 = *(const float2*)(ref + 2 * bq);
    const float rx = r2.x, ry = r2.y;

    const float* __restrict__ row = g_sa + (size_t)bq * SA_W;
    const float* __restrict__ off_row = row + warp * 24;          // (L,K,2)

    // fused softmax over 12 logits (lanes 0..11 hold values)
    float v = (lane < 12) ? row[192 + warp * 12 + lane] : -1e30f;
    float mx = v;
#pragma unroll
    for (int s = 16; s > 0; s >>= 1)
        mx = fmaxf(mx, __shfl_xor_sync(0xffffffffu, mx, s));
    float e = (lane < 12) ? __expf(v - mx) : 0.f;
    float ssum = e;
#pragma unroll
    for (int s = 16; s > 0; s >>= 1)
        ssum += __shfl_xor_sync(0xffffffffu, ssum, s);
    const float w = e * (1.f / ssum);

    const int Hs[3]    = {100, 50, 25};
    const int Ws_[3]   = {100, 50, 25};
    const int loffs[3] = {0, HW0, HW0 + HW1};

    float acc = 0.f;
#pragma unroll
    for (int l = 0; l < L_; l++) {
        const int Hh = Hs[l], Ww = Ws_[l];
        const float* projb =
            g_proj + ((size_t)b * HWTOT + loffs[l]) * C_ + warp * D_ + lane;
#pragma unroll
        for (int k = 0; k < KP_; k++) {
            const float ox = off_row[l * 8 + k * 2 + 0];
            const float oy = off_row[l * 8 + k * 2 + 1];
            const float aw = __shfl_sync(0xffffffffu, w, l * 4 + k);

            const float px = fmaf(rx, (float)Ww, ox) - 0.5f;
            const float py = fmaf(ry, (float)Hh, oy) - 0.5f;
            const float x0f = floorf(px), y0f = floorf(py);
            const int x0 = (int)x0f, y0 = (int)y0f;
            const float wx1 = px - x0f, wy1 = py - y0f;
            const float wx0 = 1.f - wx1, wy0 = 1.f - wy1;

            const bool vx0 = (x0 >= 0) && (x0 < Ww);
            const bool vx1 = (x0 + 1 >= 0) && (x0 + 1 < Ww);
            const bool vy0 = (y0 >= 0) && (y0 < Hh);
            const bool vy1 = (y0 + 1 >= 0) && (y0 + 1 < Hh);

            float s = 0.f;
            if (vy0) {
                const float* rowp = projb + (size_t)y0 * Ww * C_;
                if (vx0) s = fmaf(wx0 * wy0, rowp[(size_t)x0 * C_], s);
                if (vx1) s = fmaf(wx1 * wy0, rowp[(size_t)(x0 + 1) * C_], s);
            }
            if (vy1) {
                const float* rowp = projb + (size_t)(y0 + 1) * Ww * C_;
                if (vx0) s = fmaf(wx0 * wy1, rowp[(size_t)x0 * C_], s);
                if (vx1) s = fmaf(wx1 * wy1, rowp[(size_t)(x0 + 1) * C_], s);
            }
            acc = fmaf(aw, s, acc);
        }
    }
    mid[(size_t)bq * C_ + warp * D_ + lane] = acc;
}

// --------------------------------- launch ----------------------------------
extern "C" void kernel_launch(void* const* d_in, const int* in_sizes, int n_in,
                              void* d_out, int out_size)
{
    const float* query = (const float*)d_in[0];
    const float* refp  = (const float*)d_in[1];
    const float* v0    = (const float*)d_in[2];
    const float* v1    = (const float*)d_in[3];
    const float* v2    = (const float*)d_in[4];
    const float* Wv    = (const float*)d_in[5];
    const float* bv    = (const float*)d_in[6];
    const float* Wsmp  = (const float*)d_in[7];
    const float* bsmp  = (const float*)d_in[8];
    const float* Wa    = (const float*)d_in[9];
    const float* ba    = (const float*)d_in[10];
    const float* Wo    = (const float*)d_in[11];
    const float* bo    = (const float*)d_in[12];
    float* out = (float*)d_out;

    float *sa, *mid;
    cudaGetSymbolAddress((void**)&sa,  g_sa);
    cudaGetSymbolAddress((void**)&mid, g_mid);

    // 1) fused value projection: 2 batches * 104 pixel tiles, 2 col tiles
    {
        dim3 grid(B_ * 104, C_ / BN);
        gemm_v<<<grid, 256>>>(v0, v1, v2, Wv, bv);
    }
    // 2) fused offsets+attn GEMM: 20000 x 288
    {
        dim3 grid((NR_ + BM - 1) / BM, (SA_W + BN - 1) / BN);
        gemm_q<<<grid, 256>>>(query, NR_, Wsmp, bsmp, 192, Wa, ba, SA_W, sa);
    }
    // 3) sampling + softmax + aggregation
    sample_kernel<<<NR_, 256>>>(refp, mid);
    // 4) output projection: 20000 x 256
    {
        dim3 grid((NR_ + BM - 1) / BM, C_ / BN);
        gemm_q<<<grid, 256>>>(mid, NR_, Wo, bo, C_, Wo, bo, C_, out);
    }
}

// round 12
// speedup vs baseline: 1.9344x; 1.4510x over previous
#include <cuda_runtime.h>
#include <cuda_bf16.h>
#include <cstdint>

// ---------------------------------------------------------------------------
// MSDeformableAttention — round 9: GEMMs on warp-level mma.sync bf16
// (m16n8k16) with 2-term fp32->bf16 split (hi*hi + hi*lo + lo*hi).
// tcgen05 is unavailable (harness compiles via compute_103, no 'a' features).
//   B=2, NQ=10000, C=256, M=8, L=3, K=4, D=32; levels 100x100/50x50/25x25
// ---------------------------------------------------------------------------

#define B_    2
#define NQ_   10000
#define C_    256
#define M_    8
#define L_    3
#define KP_   4
#define D_    32
#define HW0   10000
#define HW1   2500
#define HW2   625
#define HWTOT 13125
#define NR_   (B_ * NQ_)     // 20000
#define SA_W  288            // 192 offsets + 96 attn logits per row

__device__ float g_proj[(size_t)B_ * HWTOT * C_];   // 26.9 MB, pixel-major
__device__ float g_sa  [(size_t)NR_ * SA_W];        // 23.0 MB
__device__ float g_mid [(size_t)NR_ * C_];          // 20.5 MB

// --------------------------- smem tile geometry ----------------------------
// One tile: 128 rows x 32 bf16, row stride 80 B (40 bf16).
//  - 80 is a multiple of 16 -> every ldmatrix row address is 16B-aligned.
//  - banks of row r, chunk c: (20*r + 4*c) mod 32 -> distinct for r=0..7.
#define TSTR       80
#define TILE_BYTES (128 * TSTR)        // 10240
#define OFF_AHI    0
#define OFF_ALO    (TILE_BYTES)
#define OFF_BHI    (2 * TILE_BYTES)
#define OFF_BLO    (3 * TILE_BYTES)
#define BUF_BYTES  (4 * TILE_BYTES)    // 40960
#define SMEM_BYTES (2 * BUF_BYTES)     // 81920 (double buffer)

__device__ __forceinline__ uint32_t smem_u32(const void* p) {
    uint32_t a;
    asm("{ .reg .u64 t; cvta.to.shared.u64 t, %1; cvt.u32.u64 %0, t; }"
        : "=r"(a) : "l"(p));
    return a;
}
__device__ __forceinline__ void ldsm4(uint32_t r[4], uint32_t a) {
    asm volatile("ldmatrix.sync.aligned.m8n8.x4.shared.b16 {%0,%1,%2,%3}, [%4];"
                 : "=r"(r[0]), "=r"(r[1]), "=r"(r[2]), "=r"(r[3]) : "r"(a));
}
__device__ __forceinline__ void mma_bf(float* c, const uint32_t* a,
                                       uint32_t b0, uint32_t b1) {
    asm volatile(
        "mma.sync.aligned.m16n8k16.row.col.f32.bf16.bf16.f32 "
        "{%0,%1,%2,%3}, {%4,%5,%6,%7}, {%8,%9}, {%0,%1,%2,%3};"
        : "+f"(c[0]), "+f"(c[1]), "+f"(c[2]), "+f"(c[3])
        : "r"(a[0]), "r"(a[1]), "r"(a[2]), "r"(a[3]), "r"(b0), "r"(b1));
}
__device__ __forceinline__ uint32_t pk2(__nv_bfloat16 a, __nv_bfloat16 b) {
    __nv_bfloat162 t; t.x = a; t.y = b;
    return *reinterpret_cast<uint32_t*>(&t);
}
// split a float4 (4 consecutive k) into bf16 hi/lo and store 8B each
__device__ __forceinline__ void sts_split4(char* hiP, char* loP, float4 v) {
    __nv_bfloat16 hx = __float2bfloat16(v.x), hy = __float2bfloat16(v.y);
    __nv_bfloat16 hz = __float2bfloat16(v.z), hw = __float2bfloat16(v.w);
    __nv_bfloat16 lx = __float2bfloat16(v.x - __bfloat162float(hx));
    __nv_bfloat16 ly = __float2bfloat16(v.y - __bfloat162float(hy));
    __nv_bfloat16 lz = __float2bfloat16(v.z - __bfloat162float(hz));
    __nv_bfloat16 lw = __float2bfloat16(v.w - __bfloat162float(hw));
    *reinterpret_cast<uint2*>(hiP) = make_uint2(pk2(hx, hy), pk2(hz, hw));
    *reinterpret_cast<uint2*>(loP) = make_uint2(pk2(lx, ly), pk2(lz, lw));
}
__device__ __forceinline__ void sts_split1(char* hiP, char* loP, float f) {
    __nv_bfloat16 h = __float2bfloat16(f);
    __nv_bfloat16 l = __float2bfloat16(f - __bfloat162float(h));
    *reinterpret_cast<__nv_bfloat16*>(hiP) = h;
    *reinterpret_cast<__nv_bfloat16*>(loP) = l;
}

// ------------------- per-chunk tensor-core compute (all warps) --------------
__device__ __forceinline__ void mma_compute(char* buf, int warp_m, int warp_n,
                                            int lane, float acc[2][8][4]) {
    const uint32_t AhiB = smem_u32(buf + OFF_AHI);
    const uint32_t AloB = smem_u32(buf + OFF_ALO);
    const uint32_t BhiB = smem_u32(buf + OFF_BHI);
    const uint32_t BloB = smem_u32(buf + OFF_BLO);
    const uint32_t lrow = lane & 15;
    const uint32_t lkc  = (lane >> 4) * 16;    // k-chunk byte offset (8 bf16)
#pragma unroll
    for (int ks = 0; ks < 2; ks++) {
        const uint32_t kb = ks * 32 + lkc;
        uint32_t ahi[2][4], alo[2][4];
#pragma unroll
        for (int mt = 0; mt < 2; mt++) {
            const uint32_t off = (warp_m * 32 + mt * 16 + lrow) * TSTR + kb;
            ldsm4(ahi[mt], AhiB + off);
            ldsm4(alo[mt], AloB + off);
        }
#pragma unroll
        for (int ntp = 0; ntp < 4; ntp++) {
            const uint32_t off = (warp_n * 64 + ntp * 16 + lrow) * TSTR + kb;
            uint32_t bh[4], bl[4];
            ldsm4(bh, BhiB + off);
            ldsm4(bl, BloB + off);
#pragma unroll
            for (int mt = 0; mt < 2; mt++) {
                mma_bf(acc[mt][ntp * 2],     ahi[mt], bh[0], bh[2]);
                mma_bf(acc[mt][ntp * 2],     ahi[mt], bl[0], bl[2]);
                mma_bf(acc[mt][ntp * 2],     alo[mt], bh[0], bh[2]);
                mma_bf(acc[mt][ntp * 2 + 1], ahi[mt], bh[1], bh[3]);
                mma_bf(acc[mt][ntp * 2 + 1], ahi[mt], bl[1], bl[3]);
                mma_bf(acc[mt][ntp * 2 + 1], alo[mt], bh[1], bh[3]);
            }
        }
    }
}

// ---------------- row-major A GEMM (query-side): Y = X @ [W1;W2]^T ----------
__global__ __launch_bounds__(256) void mma_gemm_rowA(
    const float* __restrict__ X, int Nrows,
    const float* __restrict__ W1, const float* __restrict__ b1, int O1,
    const float* __restrict__ W2, const float* __restrict__ b2, int Otot,
    float* __restrict__ Y, int ldy)
{
    extern __shared__ char smem[];
    const int tid = threadIdx.x, wid = tid >> 5, lane = tid & 31;
    const int warp_m = wid & 3, warp_n = wid >> 2;
    const int m0 = blockIdx.x * 128, col0 = blockIdx.y * 128;

    const int lr = tid >> 1, lk = (tid & 1) * 16;
    const float* __restrict__ xrow =
        (m0 + lr < Nrows) ? X + (size_t)(m0 + lr) * C_ : nullptr;
    const int oG = col0 + lr;
    const float* __restrict__ wrow =
        (oG < O1) ? W1 + (size_t)oG * C_
                  : ((oG < Otot) ? W2 + (size_t)(oG - O1) * C_ : nullptr);
    const float4 z4 = make_float4(0.f, 0.f, 0.f, 0.f);

    float4 aS[4], bS[4];
#pragma unroll
    for (int i = 0; i < 4; i++) {
        aS[i] = xrow ? *(const float4*)(xrow + lk + 4 * i) : z4;
        bS[i] = wrow ? *(const float4*)(wrow + lk + 4 * i) : z4;
    }
    {
        char* buf = smem;
#pragma unroll
        for (int i = 0; i < 4; i++) {
            const int kb = (lk + 4 * i) * 2;
            sts_split4(buf + OFF_AHI + lr * TSTR + kb,
                       buf + OFF_ALO + lr * TSTR + kb, aS[i]);
            sts_split4(buf + OFF_BHI + lr * TSTR + kb,
                       buf + OFF_BLO + lr * TSTR + kb, bS[i]);
        }
    }
    __syncthreads();

    float acc[2][8][4];
#pragma unroll
    for (int mt = 0; mt < 2; mt++)
#pragma unroll
        for (int nt = 0; nt < 8; nt++)
#pragma unroll
            for (int i = 0; i < 4; i++) acc[mt][nt][i] = 0.f;

    for (int ch = 0; ch < 8; ch++) {
        if (ch < 7) {
            const int k0 = (ch + 1) * 32;
#pragma unroll
            for (int i = 0; i < 4; i++) {
                aS[i] = xrow ? *(const float4*)(xrow + k0 + lk + 4 * i) : z4;
                bS[i] = wrow ? *(const float4*)(wrow + k0 + lk + 4 * i) : z4;
            }
        }
        mma_compute(smem + (ch & 1) * BUF_BYTES, warp_m, warp_n, lane, acc);
        if (ch < 7) {
            char* nb = smem + ((ch + 1) & 1) * BUF_BYTES;
#pragma unroll
            for (int i = 0; i < 4; i++) {
                const int kb = (lk + 4 * i) * 2;
                sts_split4(nb + OFF_AHI + lr * TSTR + kb,
                           nb + OFF_ALO + lr * TSTR + kb, aS[i]);
                sts_split4(nb + OFF_BHI + lr * TSTR + kb,
                           nb + OFF_BLO + lr * TSTR + kb, bS[i]);
            }
            __syncthreads();
        }
    }

    // epilogue: c0,c1 -> (row r0, col c..c+1); c2,c3 -> (row r0+8, col c..c+1)
#pragma unroll
    for (int mt = 0; mt < 2; mt++) {
        const int r0 = m0 + warp_m * 32 + mt * 16 + (lane >> 2);
#pragma unroll
        for (int nt = 0; nt < 8; nt++) {
            const int c = col0 + warp_n * 64 + nt * 8 + (lane & 3) * 2;
            if (c >= Otot) continue;
            const float bv0 = (c < O1) ? b1[c] : b2[c - O1];
            const float bv1 = (c + 1 < O1) ? b1[c + 1] : b2[c + 1 - O1];
            if (r0 < Nrows)
                *(float2*)(Y + (size_t)r0 * ldy + c) =
                    make_float2(acc[mt][nt][0] + bv0, acc[mt][nt][1] + bv1);
            if (r0 + 8 < Nrows)
                *(float2*)(Y + (size_t)(r0 + 8) * ldy + c) =
                    make_float2(acc[mt][nt][2] + bv0, acc[mt][nt][3] + bv1);
        }
    }
}

// ------------- value projection GEMM: A = V (C,HW) channel-major ------------
// blockIdx.x = b*104 + tile (79 + 20 + 5 pixel tiles); blockIdx.y = col tile.
__global__ __launch_bounds__(256) void mma_gemm_v(
    const float* __restrict__ V0, const float* __restrict__ V1,
    const float* __restrict__ V2, const float* __restrict__ Wv,
    const float* __restrict__ bv)
{
    extern __shared__ char smem[];
    const int tid = threadIdx.x, wid = tid >> 5, lane = tid & 31;
    const int warp_m = wid & 3, warp_n = wid >> 2;
    const int bx = blockIdx.x;
    const int b  = bx / 104;
    const int tl = bx - b * 104;
    int p0, HW, loff;
    const float* A;
    if (tl < 79)      { p0 = tl * 128;        HW = HW0; loff = 0;         A = V0; }
    else if (tl < 99) { p0 = (tl - 79) * 128; HW = HW1; loff = HW0;       A = V1; }
    else              { p0 = (tl - 99) * 128; HW = HW2; loff = HW0 + HW1; A = V2; }
    A += (size_t)b * C_ * HW;
    const int col0 = blockIdx.y * 128;

    // A loader: channel cL = tid>>3 (0..31), 16 consecutive pixels at (tid&7)*16
    const int cL = tid >> 3;
    const int pb = (tid & 7) * 16;
    const bool vecOK = ((HW & 3) == 0) && (p0 + pb + 15 < HW);
    // B loader: standard
    const int lr = tid >> 1, lk = (tid & 1) * 16;
    const float* __restrict__ wrow = Wv + (size_t)(col0 + lr) * C_;

    float aV[16];
    float4 bS[4];

    // chunk 0 load
    {
        const float* src = A + (size_t)cL * HW + p0 + pb;
        if (vecOK) {
#pragma unroll
            for (int i = 0; i < 4; i++) {
                float4 v = *(const float4*)(src + 4 * i);
                aV[4*i] = v.x; aV[4*i+1] = v.y; aV[4*i+2] = v.z; aV[4*i+3] = v.w;
            }
        } else {
#pragma unroll
            for (int i = 0; i < 16; i++)
                aV[i] = (p0 + pb + i < HW) ? src[i] : 0.f;
        }
#pragma unroll
        for (int i = 0; i < 4; i++)
            bS[i] = *(const float4*)(wrow + lk + 4 * i);
    }
    {
        char* buf = smem;
#pragma unroll
        for (int i = 0; i < 16; i++)
            sts_split1(buf + OFF_AHI + (pb + i) * TSTR + cL * 2,
                       buf + OFF_ALO + (pb + i) * TSTR + cL * 2, aV[i]);
#pragma unroll
        for (int i = 0; i < 4; i++) {
            const int kb = (lk + 4 * i) * 2;
            sts_split4(buf + OFF_BHI + lr * TSTR + kb,
                       buf + OFF_BLO + lr * TSTR + kb, bS[i]);
        }
    }
    __syncthreads();

    float acc[2][8][4];
#pragma unroll
    for (int mt = 0; mt < 2; mt++)
#pragma unroll
        for (int nt = 0; nt < 8; nt++)
#pragma unroll
            for (int i = 0; i < 4; i++) acc[mt][nt][i] = 0.f;

    for (int ch = 0; ch < 8; ch++) {
        if (ch < 7) {
            const int k0 = (ch + 1) * 32;
            const float* src = A + (size_t)(k0 + cL) * HW + p0 + pb;
            if (vecOK) {
#pragma unroll
                for (int i = 0; i < 4; i++) {
                    float4 v = *(const float4*)(src + 4 * i);
                    aV[4*i] = v.x; aV[4*i+1] = v.y;
                    aV[4*i+2] = v.z; aV[4*i+3] = v.w;
                }
            } else {
#pragma unroll
                for (int i = 0; i < 16; i++)
                    aV[i] = (p0 + pb + i < HW) ? src[i] : 0.f;
            }
#pragma unroll
            for (int i = 0; i < 4; i++)
                bS[i] = *(const float4*)(wrow + k0 + lk + 4 * i);
        }
        mma_compute(smem + (ch & 1) * BUF_BYTES, warp_m, warp_n, lane, acc);
        if (ch < 7) {
            char* nb = smem + ((ch + 1) & 1) * BUF_BYTES;
#pragma unroll
            for (int i = 0; i < 16; i++)
                sts_split1(nb + OFF_AHI + (pb + i) * TSTR + cL * 2,
                           nb + OFF_ALO + (pb + i) * TSTR + cL * 2, aV[i]);
#pragma unroll
            for (int i = 0; i < 4; i++) {
                const int kb = (lk + 4 * i) * 2;
                sts_split4(nb + OFF_BHI + lr * TSTR + kb,
                           nb + OFF_BLO + lr * TSTR + kb, bS[i]);
            }
            __syncthreads();
        }
    }

    float* __restrict__ Y = g_proj + (size_t)(b * HWTOT + loff) * C_;
#pragma unroll
    for (int mt = 0; mt < 2; mt++) {
        const int r0 = warp_m * 32 + mt * 16 + (lane >> 2);
#pragma unroll
        for (int nt = 0; nt < 8; nt++) {
            const int c = col0 + warp_n * 64 + nt * 8 + (lane & 3) * 2;
            const float bv0 = bv[c], bv1 = bv[c + 1];
            if (p0 + r0 < HW)
                *(float2*)(Y + (size_t)(p0 + r0) * C_ + c) =
                    make_float2(acc[mt][nt][0] + bv0, acc[mt][nt][1] + bv1);
            if (p0 + r0 + 8 < HW)
                *(float2*)(Y + (size_t)(p0 + r0 + 8) * C_ + c) =
                    make_float2(acc[mt][nt][2] + bv0, acc[mt][nt][3] + bv1);
        }
    }
}

// ------------- bilinear sampling + aggregation, softmax fused ---------------
__global__ __launch_bounds__(256) void sample_kernel(
    const float* __restrict__ ref, float* __restrict__ mid)
{
    const int bq   = blockIdx.x;
    const int b    = bq / NQ_;
    const int warp = threadIdx.x >> 5;
    const int lane = threadIdx.x & 31;

    const float2 r2 = *(const float2*)(ref + 2 * bq);
    const float rx = r2.x, ry = r2.y;

    const float* __restrict__ row = g_sa + (size_t)bq * SA_W;
    const float* __restrict__ off_row = row + warp * 24;          // (L,K,2)

    float v = (lane < 12) ? row[192 + warp * 12 + lane] : -1e30f;
    float mx = v;
#pragma unroll
    for (int s = 16; s > 0; s >>= 1)
        mx = fmaxf(mx, __shfl_xor_sync(0xffffffffu, mx, s));
    float e = (lane < 12) ? __expf(v - mx) : 0.f;
    float ssum = e;
#pragma unroll
    for (int s = 16; s > 0; s >>= 1)
        ssum += __shfl_xor_sync(0xffffffffu, ssum, s);
    const float w = e * (1.f / ssum);

    const int Hs[3]    = {100, 50, 25};
    const int Ws_[3]   = {100, 50, 25};
    const int loffs[3] = {0, HW0, HW0 + HW1};

    float acc = 0.f;
#pragma unroll
    for (int l = 0; l < L_; l++) {
        const int Hh = Hs[l], Ww = Ws_[l];
        const float* projb =
            g_proj + ((size_t)b * HWTOT + loffs[l]) * C_ + warp * D_ + lane;
#pragma unroll
        for (int k = 0; k < KP_; k++) {
            const float ox = off_row[l * 8 + k * 2 + 0];
            const float oy = off_row[l * 8 + k * 2 + 1];
            const float aw = __shfl_sync(0xffffffffu, w, l * 4 + k);

            const float px = fmaf(rx, (float)Ww, ox) - 0.5f;
            const float py = fmaf(ry, (float)Hh, oy) - 0.5f;
            const float x0f = floorf(px), y0f = floorf(py);
            const int x0 = (int)x0f, y0 = (int)y0f;
            const float wx1 = px - x0f, wy1 = py - y0f;
            const float wx0 = 1.f - wx1, wy0 = 1.f - wy1;

            const bool vx0 = (x0 >= 0) && (x0 < Ww);
            const bool vx1 = (x0 + 1 >= 0) && (x0 + 1 < Ww);
            const bool vy0 = (y0 >= 0) && (y0 < Hh);
            const bool vy1 = (y0 + 1 >= 0) && (y0 + 1 < Hh);

            float s = 0.f;
            if (vy0) {
                const float* rowp = projb + (size_t)y0 * Ww * C_;
                if (vx0) s = fmaf(wx0 * wy0, rowp[(size_t)x0 * C_], s);
                if (vx1) s = fmaf(wx1 * wy0, rowp[(size_t)(x0 + 1) * C_], s);
            }
            if (vy1) {
                const float* rowp = projb + (size_t)(y0 + 1) * Ww * C_;
                if (vx0) s = fmaf(wx0 * wy1, rowp[(size_t)x0 * C_], s);
                if (vx1) s = fmaf(wx1 * wy1, rowp[(size_t)(x0 + 1) * C_], s);
            }
            acc = fmaf(aw, s, acc);
        }
    }
    mid[(size_t)bq * C_ + warp * D_ + lane] = acc;
}

// --------------------------------- launch ----------------------------------
extern "C" void kernel_launch(void* const* d_in, const int* in_sizes, int n_in,
                              void* d_out, int out_size)
{
    const float* query = (const float*)d_in[0];
    const float* refp  = (const float*)d_in[1];
    const float* v0    = (const float*)d_in[2];
    const float* v1    = (const float*)d_in[3];
    const float* v2    = (const float*)d_in[4];
    const float* Wv    = (const float*)d_in[5];
    const float* bv    = (const float*)d_in[6];
    const float* Wsmp  = (const float*)d_in[7];
    const float* bsmp  = (const float*)d_in[8];
    const float* Wa    = (const float*)d_in[9];
    const float* ba    = (const float*)d_in[10];
    const float* Wo    = (const float*)d_in[11];
    const float* bo    = (const float*)d_in[12];
    float* out = (float*)d_out;

    float *sa, *mid;
    cudaGetSymbolAddress((void**)&sa,  g_sa);
    cudaGetSymbolAddress((void**)&mid, g_mid);

    cudaFuncSetAttribute(mma_gemm_rowA,
        cudaFuncAttributeMaxDynamicSharedMemorySize, SMEM_BYTES);
    cudaFuncSetAttribute(mma_gemm_v,
        cudaFuncAttributeMaxDynamicSharedMemorySize, SMEM_BYTES);

    // 1) value projection: (2 batches * 104 pixel tiles) x 2 col tiles
    {
        dim3 grid(B_ * 104, 2);
        mma_gemm_v<<<grid, 256, SMEM_BYTES>>>(v0, v1, v2, Wv, bv);
    }
    // 2) fused offsets+attn GEMM: 20000 x 288 (157 x 3 tiles, ragged cols)
    {
        dim3 grid((NR_ + 127) / 128, 3);
        mma_gemm_rowA<<<grid, 256, SMEM_BYTES>>>(
            query, NR_, Wsmp, bsmp, 192, Wa, ba, SA_W, sa, SA_W);
    }
    // 3) sampling + softmax + aggregation
    sample_kernel<<<NR_, 256>>>(refp, mid);
    // 4) output projection: 20000 x 256 (157 x 2 tiles)
    {
        dim3 grid((NR_ + 127) / 128, 2);
        mma_gemm_rowA<<<grid, 256, SMEM_BYTES>>>(
            mid, NR_, Wo, bo, C_, Wo, bo, C_, out, C_);
    }
}

// round 15
// speedup vs baseline: 2.0287x; 1.0487x over previous
#include <cuda_runtime.h>
#include <cuda_bf16.h>
#include <cstdint>

// ---------------------------------------------------------------------------
// MSDeformableAttention — round 12 design (resubmitted after infra failure):
// mma.sync bf16 3-product GEMMs retiled to 128x64 CTA / 32x32 warp for
// 2 CTAs/SM; value-proj + offs/attn GEMMs fused into one launch.
//   B=2, NQ=10000, C=256, M=8, L=3, K=4, D=32; levels 100x100/50x50/25x25
// ---------------------------------------------------------------------------

#define B_    2
#define NQ_   10000
#define C_    256
#define M_    8
#define L_    3
#define KP_   4
#define D_    32
#define HW0   10000
#define HW1   2500
#define HW2   625
#define HWTOT 13125
#define NR_   (B_ * NQ_)     // 20000
#define SA_W  288            // 192 offsets + 96 attn logits per row

__device__ float g_proj[(size_t)B_ * HWTOT * C_];   // 26.9 MB, pixel-major
__device__ float g_sa  [(size_t)NR_ * SA_W];        // 23.0 MB
__device__ float g_mid [(size_t)NR_ * C_];          // 20.5 MB

// --------------------------- smem tile geometry ----------------------------
// Row stride 80 B: multiple of 16 (ldmatrix) and conflict-free across 8 rows.
#define TSTR       80
#define A_TILE     (128 * TSTR)        // 10240
#define B_TILE     (64 * TSTR)         // 5120
#define OFF_AHI    0
#define OFF_ALO    (A_TILE)
#define OFF_BHI    (2 * A_TILE)
#define OFF_BLO    (2 * A_TILE + B_TILE)
#define BUF_BYTES  (2 * A_TILE + 2 * B_TILE)   // 30720
#define SMEM_BYTES (2 * BUF_BYTES)             // 61440 (double buffer)

// value-proj block range in the fused launch
#define NVB        (208 * 4)           // 832
#define NQB        (157 * 5)           // 785
#define FUSED_GRID (NVB + NQB)

__device__ __forceinline__ uint32_t smem_u32(const void* p) {
    uint32_t a;
    asm("{ .reg .u64 t; cvta.to.shared.u64 t, %1; cvt.u32.u64 %0, t; }"
        : "=r"(a) : "l"(p));
    return a;
}
__device__ __forceinline__ void ldsm4(uint32_t r[4], uint32_t a) {
    asm volatile("ldmatrix.sync.aligned.m8n8.x4.shared.b16 {%0,%1,%2,%3}, [%4];"
                 : "=r"(r[0]), "=r"(r[1]), "=r"(r[2]), "=r"(r[3]) : "r"(a));
}
__device__ __forceinline__ void mma_bf(float* c, const uint32_t* a,
                                       uint32_t b0, uint32_t b1) {
    asm volatile(
        "mma.sync.aligned.m16n8k16.row.col.f32.bf16.bf16.f32 "
        "{%0,%1,%2,%3}, {%4,%5,%6,%7}, {%8,%9}, {%0,%1,%2,%3};"
        : "+f"(c[0]), "+f"(c[1]), "+f"(c[2]), "+f"(c[3])
        : "r"(a[0]), "r"(a[1]), "r"(a[2]), "r"(a[3]), "r"(b0), "r"(b1));
}
__device__ __forceinline__ uint32_t pk2(__nv_bfloat16 a, __nv_bfloat16 b) {
    __nv_bfloat162 t; t.x = a; t.y = b;
    return *reinterpret_cast<uint32_t*>(&t);
}
__device__ __forceinline__ void sts_split4(char* hiP, char* loP, float4 v) {
    __nv_bfloat16 hx = __float2bfloat16(v.x), hy = __float2bfloat16(v.y);
    __nv_bfloat16 hz = __float2bfloat16(v.z), hw = __float2bfloat16(v.w);
    __nv_bfloat16 lx = __float2bfloat16(v.x - __bfloat162float(hx));
    __nv_bfloat16 ly = __float2bfloat16(v.y - __bfloat162float(hy));
    __nv_bfloat16 lz = __float2bfloat16(v.z - __bfloat162float(hz));
    __nv_bfloat16 lw = __float2bfloat16(v.w - __bfloat162float(hw));
    *reinterpret_cast<uint2*>(hiP) = make_uint2(pk2(hx, hy), pk2(hz, hw));
    *reinterpret_cast<uint2*>(loP) = make_uint2(pk2(lx, ly), pk2(lz, lw));
}
__device__ __forceinline__ void sts_split1(char* hiP, char* loP, float f) {
    __nv_bfloat16 h = __float2bfloat16(f);
    __nv_bfloat16 l = __float2bfloat16(f - __bfloat162float(h));
    *reinterpret_cast<__nv_bfloat16*>(hiP) = h;
    *reinterpret_cast<__nv_bfloat16*>(loP) = l;
}

// -------------- per-chunk tensor compute: 128x64 CTA, 32x32 warp ------------
__device__ __forceinline__ void mma_compute64(char* buf, int warp_m, int warp_n,
                                              int lane, float acc[2][4][4]) {
    const uint32_t AhiB = smem_u32(buf + OFF_AHI);
    const uint32_t AloB = smem_u32(buf + OFF_ALO);
    const uint32_t BhiB = smem_u32(buf + OFF_BHI);
    const uint32_t BloB = smem_u32(buf + OFF_BLO);
    const uint32_t lrow = lane & 15;
    const uint32_t lkc  = (lane >> 4) * 16;   // k half-chunk byte offset
#pragma unroll
    for (int ks = 0; ks < 2; ks++) {
        const uint32_t kb = ks * 32 + lkc;
        uint32_t ahi[2][4], alo[2][4];
#pragma unroll
        for (int mt = 0; mt < 2; mt++) {
            const uint32_t off = (warp_m * 32 + mt * 16 + lrow) * TSTR + kb;
            ldsm4(ahi[mt], AhiB + off);
            ldsm4(alo[mt], AloB + off);
        }
#pragma unroll
        for (int ntp = 0; ntp < 2; ntp++) {
            const uint32_t off = (warp_n * 32 + ntp * 16 + lrow) * TSTR + kb;
            uint32_t bh[4], bl[4];
            ldsm4(bh, BhiB + off);
            ldsm4(bl, BloB + off);
#pragma unroll
            for (int mt = 0; mt < 2; mt++) {
                mma_bf(acc[mt][ntp * 2],     ahi[mt], bh[0], bh[2]);
                mma_bf(acc[mt][ntp * 2],     ahi[mt], bl[0], bl[2]);
                mma_bf(acc[mt][ntp * 2],     alo[mt], bh[0], bh[2]);
                mma_bf(acc[mt][ntp * 2 + 1], ahi[mt], bh[1], bh[3]);
                mma_bf(acc[mt][ntp * 2 + 1], ahi[mt], bl[1], bl[3]);
                mma_bf(acc[mt][ntp * 2 + 1], alo[mt], bh[1], bh[3]);
            }
        }
    }
}

// ---------------- row-major-A GEMM body: Y = X @ [W1;W2]^T + bias -----------
__device__ __forceinline__ void gemm_rowA_body(
    char* smem, int m0, int col0,
    const float* __restrict__ X, int Nrows,
    const float* __restrict__ W1, const float* __restrict__ b1, int O1,
    const float* __restrict__ W2, const float* __restrict__ b2, int Otot,
    float* __restrict__ Y, int ldy)
{
    const int tid = threadIdx.x, wid = tid >> 5, lane = tid & 31;
    const int warp_m = wid & 3, warp_n = wid >> 2;

    // A loader: 128 rows x 32 k, 4 float4 per thread
    const int lr = tid >> 1, lk = (tid & 1) * 16;
    const float* __restrict__ xrow =
        (m0 + lr < Nrows) ? X + (size_t)(m0 + lr) * C_ : nullptr;
    // B loader: 64 rows x 32 k, 2 float4 per thread
    const int rB = tid >> 2, kB = (tid & 3) * 8;
    const int oG = col0 + rB;
    const float* __restrict__ wrow =
        (oG < O1) ? W1 + (size_t)oG * C_
                  : ((oG < Otot) ? W2 + (size_t)(oG - O1) * C_ : nullptr);
    const float4 z4 = make_float4(0.f, 0.f, 0.f, 0.f);

    float4 aS[4], bS[2];
#pragma unroll
    for (int i = 0; i < 4; i++)
        aS[i] = xrow ? *(const float4*)(xrow + lk + 4 * i) : z4;
#pragma unroll
    for (int i = 0; i < 2; i++)
        bS[i] = wrow ? *(const float4*)(wrow + kB + 4 * i) : z4;
    {
        char* buf = smem;
#pragma unroll
        for (int i = 0; i < 4; i++) {
            const int kb = (lk + 4 * i) * 2;
            sts_split4(buf + OFF_AHI + lr * TSTR + kb,
                       buf + OFF_ALO + lr * TSTR + kb, aS[i]);
        }
#pragma unroll
        for (int i = 0; i < 2; i++) {
            const int kb = (kB + 4 * i) * 2;
            sts_split4(buf + OFF_BHI + rB * TSTR + kb,
                       buf + OFF_BLO + rB * TSTR + kb, bS[i]);
        }
    }
    __syncthreads();

    float acc[2][4][4];
#pragma unroll
    for (int mt = 0; mt < 2; mt++)
#pragma unroll
        for (int nt = 0; nt < 4; nt++)
#pragma unroll
            for (int i = 0; i < 4; i++) acc[mt][nt][i] = 0.f;

    for (int ch = 0; ch < 8; ch++) {
        if (ch < 7) {
            const int k0 = (ch + 1) * 32;
#pragma unroll
            for (int i = 0; i < 4; i++)
                aS[i] = xrow ? *(const float4*)(xrow + k0 + lk + 4 * i) : z4;
#pragma unroll
            for (int i = 0; i < 2; i++)
                bS[i] = wrow ? *(const float4*)(wrow + k0 + kB + 4 * i) : z4;
        }
        mma_compute64(smem + (ch & 1) * BUF_BYTES, warp_m, warp_n, lane, acc);
        if (ch < 7) {
            char* nb = smem + ((ch + 1) & 1) * BUF_BYTES;
#pragma unroll
            for (int i = 0; i < 4; i++) {
                const int kb = (lk + 4 * i) * 2;
                sts_split4(nb + OFF_AHI + lr * TSTR + kb,
                           nb + OFF_ALO + lr * TSTR + kb, aS[i]);
            }
#pragma unroll
            for (int i = 0; i < 2; i++) {
                const int kb = (kB + 4 * i) * 2;
                sts_split4(nb + OFF_BHI + rB * TSTR + kb,
                           nb + OFF_BLO + rB * TSTR + kb, bS[i]);
            }
            __syncthreads();
        }
    }

#pragma unroll
    for (int mt = 0; mt < 2; mt++) {
        const int r0 = m0 + warp_m * 32 + mt * 16 + (lane >> 2);
#pragma unroll
        for (int nt = 0; nt < 4; nt++) {
            const int c = col0 + warp_n * 32 + nt * 8 + (lane & 3) * 2;
            if (c >= Otot) continue;
            const float bv0 = (c < O1) ? b1[c] : b2[c - O1];
            const float bv1 = (c + 1 < O1) ? b1[c + 1] : b2[c + 1 - O1];
            if (r0 < Nrows)
                *(float2*)(Y + (size_t)r0 * ldy + c) =
                    make_float2(acc[mt][nt][0] + bv0, acc[mt][nt][1] + bv1);
            if (r0 + 8 < Nrows)
                *(float2*)(Y + (size_t)(r0 + 8) * ldy + c) =
                    make_float2(acc[mt][nt][2] + bv0, acc[mt][nt][3] + bv1);
        }
    }
}

// ------------- value-projection GEMM body: A = V (C,HW) channel-major -------
__device__ __forceinline__ void gemm_v_body(
    char* smem, int vbid,
    const float* __restrict__ V0, const float* __restrict__ V1,
    const float* __restrict__ V2, const float* __restrict__ Wv,
    const float* __restrict__ bv)
{
    const int tid = threadIdx.x, wid = tid >> 5, lane = tid & 31;
    const int warp_m = wid & 3, warp_n = wid >> 2;
    const int xt = vbid >> 2;             // 0..207
    const int col0 = (vbid & 3) * 64;
    const int b  = xt / 104;
    const int tl = xt - b * 104;
    int p0, HW, loff;
    const float* A;
    if (tl < 79)      { p0 = tl * 128;        HW = HW0; loff = 0;         A = V0; }
    else if (tl < 99) { p0 = (tl - 79) * 128; HW = HW1; loff = HW0;       A = V1; }
    else              { p0 = (tl - 99) * 128; HW = HW2; loff = HW0 + HW1; A = V2; }
    A += (size_t)b * C_ * HW;

    // A loader: channel cL (0..31), 16 consecutive pixels at (tid&7)*16
    const int cL = tid >> 3;
    const int pb = (tid & 7) * 16;
    const bool vecOK = ((HW & 3) == 0) && (p0 + pb + 15 < HW);
    // B loader: 64 rows x 32 k
    const int rB = tid >> 2, kB = (tid & 3) * 8;
    const float* __restrict__ wrow = Wv + (size_t)(col0 + rB) * C_;

    float aV[16];
    float4 bS[2];
    {
        const float* src = A + (size_t)cL * HW + p0 + pb;
        if (vecOK) {
#pragma unroll
            for (int i = 0; i < 4; i++) {
                float4 v = *(const float4*)(src + 4 * i);
                aV[4*i] = v.x; aV[4*i+1] = v.y; aV[4*i+2] = v.z; aV[4*i+3] = v.w;
            }
        } else {
#pragma unroll
            for (int i = 0; i < 16; i++)
                aV[i] = (p0 + pb + i < HW) ? src[i] : 0.f;
        }
#pragma unroll
        for (int i = 0; i < 2; i++)
            bS[i] = *(const float4*)(wrow + kB + 4 * i);
    }
    {
        char* buf = smem;
#pragma unroll
        for (int i = 0; i < 16; i++)
            sts_split1(buf + OFF_AHI + (pb + i) * TSTR + cL * 2,
                       buf + OFF_ALO + (pb + i) * TSTR + cL * 2, aV[i]);
#pragma unroll
        for (int i = 0; i < 2; i++) {
            const int kb = (kB + 4 * i) * 2;
            sts_split4(buf + OFF_BHI + rB * TSTR + kb,
                       buf + OFF_BLO + rB * TSTR + kb, bS[i]);
        }
    }
    __syncthreads();

    float acc[2][4][4];
#pragma unroll
    for (int mt = 0; mt < 2; mt++)
#pragma unroll
        for (int nt = 0; nt < 4; nt++)
#pragma unroll
            for (int i = 0; i < 4; i++) acc[mt][nt][i] = 0.f;

    for (int ch = 0; ch < 8; ch++) {
        if (ch < 7) {
            const int k0 = (ch + 1) * 32;
            const float* src = A + (size_t)(k0 + cL) * HW + p0 + pb;
            if (vecOK) {
#pragma unroll
                for (int i = 0; i < 4; i++) {
                    float4 v = *(const float4*)(src + 4 * i);
                    aV[4*i] = v.x; aV[4*i+1] = v.y;
                    aV[4*i+2] = v.z; aV[4*i+3] = v.w;
                }
            } else {
#pragma unroll
                for (int i = 0; i < 16; i++)
                    aV[i] = (p0 + pb + i < HW) ? src[i] : 0.f;
            }
#pragma unroll
            for (int i = 0; i < 2; i++)
                bS[i] = *(const float4*)(wrow + k0 + kB + 4 * i);
        }
        mma_compute64(smem + (ch & 1) * BUF_BYTES, warp_m, warp_n, lane, acc);
        if (ch < 7) {
            char* nb = smem + ((ch + 1) & 1) * BUF_BYTES;
#pragma unroll
            for (int i = 0; i < 16; i++)
                sts_split1(nb + OFF_AHI + (pb + i) * TSTR + cL * 2,
                           nb + OFF_ALO + (pb + i) * TSTR + cL * 2, aV[i]);
#pragma unroll
            for (int i = 0; i < 2; i++) {
                const int kb = (kB + 4 * i) * 2;
                sts_split4(nb + OFF_BHI + rB * TSTR + kb,
                           nb + OFF_BLO + rB * TSTR + kb, bS[i]);
            }
            __syncthreads();
        }
    }

    float* __restrict__ Y = g_proj + (size_t)(b * HWTOT + loff) * C_;
#pragma unroll
    for (int mt = 0; mt < 2; mt++) {
        const int r0 = warp_m * 32 + mt * 16 + (lane >> 2);
#pragma unroll
        for (int nt = 0; nt < 4; nt++) {
            const int c = col0 + warp_n * 32 + nt * 8 + (lane & 3) * 2;
            const float bv0 = bv[c], bv1 = bv[c + 1];
            if (p0 + r0 < HW)
                *(float2*)(Y + (size_t)(p0 + r0) * C_ + c) =
                    make_float2(acc[mt][nt][0] + bv0, acc[mt][nt][1] + bv1);
            if (p0 + r0 + 8 < HW)
                *(float2*)(Y + (size_t)(p0 + r0 + 8) * C_ + c) =
                    make_float2(acc[mt][nt][2] + bv0, acc[mt][nt][3] + bv1);
        }
    }
}

// ------------------ fused launch 1: value proj + offs/attn ------------------
__global__ __launch_bounds__(256, 2) void gemm_fused1(
    const float* __restrict__ V0, const float* __restrict__ V1,
    const float* __restrict__ V2, const float* __restrict__ Wv,
    const float* __restrict__ bv,
    const float* __restrict__ query,
    const float* __restrict__ Wsmp, const float* __restrict__ bsmp,
    const float* __restrict__ Wa,   const float* __restrict__ ba,
    float* __restrict__ sa)
{
    extern __shared__ char smem[];
    const int bid = blockIdx.x;
    if (bid < NVB) {
        gemm_v_body(smem, bid, V0, V1, V2, Wv, bv);
    } else {
        const int q = bid - NVB;
        const int xt = q / 5, yt = q - xt * 5;
        gemm_rowA_body(smem, xt * 128, yt * 64, query, NR_,
                       Wsmp, bsmp, 192, Wa, ba, SA_W, sa, SA_W);
    }
}

// --------------------------- output projection ------------------------------
__global__ __launch_bounds__(256, 2) void gemm_out(
    const float* __restrict__ X, const float* __restrict__ Wo,
    const float* __restrict__ bo, float* __restrict__ Y)
{
    extern __shared__ char smem[];
    gemm_rowA_body(smem, blockIdx.x * 128, blockIdx.y * 64, X, NR_,
                   Wo, bo, C_, Wo, bo, C_, Y, C_);
}

// ------------- bilinear sampling + aggregation, softmax fused ---------------
__global__ __launch_bounds__(256) void sample_kernel(
    const float* __restrict__ ref, float* __restrict__ mid)
{
    const int bq   = blockIdx.x;
    const int b    = bq / NQ_;
    const int warp = threadIdx.x >> 5;
    const int lane = threadIdx.x & 31;

    const float2 r2 = *(const float2*)(ref + 2 * bq);
    const float rx = r2.x, ry = r2.y;

    const float* __restrict__ row = g_sa + (size_t)bq * SA_W;
    const float* __restrict__ off_row = row + warp * 24;          // (L,K,2)

    float v = (lane < 12) ? row[192 + warp * 12 + lane] : -1e30f;
    float mx = v;
#pragma unroll
    for (int s = 16; s > 0; s >>= 1)
        mx = fmaxf(mx, __shfl_xor_sync(0xffffffffu, mx, s));
    float e = (lane < 12) ? __expf(v - mx) : 0.f;
    float ssum = e;
#pragma unroll
    for (int s = 16; s > 0; s >>= 1)
        ssum += __shfl_xor_sync(0xffffffffu, ssum, s);
    const float w = e * (1.f / ssum);

    const int Hs[3]    = {100, 50, 25};
    const int Ws_[3]   = {100, 50, 25};
    const int loffs[3] = {0, HW0, HW0 + HW1};

    float acc = 0.f;
#pragma unroll
    for (int l = 0; l < L_; l++) {
        const int Hh = Hs[l], Ww = Ws_[l];
        const float* projb =
            g_proj + ((size_t)b * HWTOT + loffs[l]) * C_ + warp * D_ + lane;
#pragma unroll
        for (int k = 0; k < KP_; k++) {
            const float ox = off_row[l * 8 + k * 2 + 0];
            const float oy = off_row[l * 8 + k * 2 + 1];
            const float aw = __shfl_sync(0xffffffffu, w, l * 4 + k);

            const float px = fmaf(rx, (float)Ww, ox) - 0.5f;
            const float py = fmaf(ry, (float)Hh, oy) - 0.5f;
            const float x0f = floorf(px), y0f = floorf(py);
            const int x0 = (int)x0f, y0 = (int)y0f;
            const float wx1 = px - x0f, wy1 = py - y0f;
            const float wx0 = 1.f - wx1, wy0 = 1.f - wy1;

            const bool vx0 = (x0 >= 0) && (x0 < Ww);
            const bool vx1 = (x0 + 1 >= 0) && (x0 + 1 < Ww);
            const bool vy0 = (y0 >= 0) && (y0 < Hh);
            const bool vy1 = (y0 + 1 >= 0) && (y0 + 1 < Hh);

            float s = 0.f;
            if (vy0) {
                const float* rowp = projb + (size_t)y0 * Ww * C_;
                if (vx0) s = fmaf(wx0 * wy0, rowp[(size_t)x0 * C_], s);
                if (vx1) s = fmaf(wx1 * wy0, rowp[(size_t)(x0 + 1) * C_], s);
            }
            if (vy1) {
                const float* rowp = projb + (size_t)(y0 + 1) * Ww * C_;
                if (vx0) s = fmaf(wx0 * wy1, rowp[(size_t)x0 * C_], s);
                if (vx1) s = fmaf(wx1 * wy1, rowp[(size_t)(x0 + 1) * C_], s);
            }
            acc = fmaf(aw, s, acc);
        }
    }
    mid[(size_t)bq * C_ + warp * D_ + lane] = acc;
}

// --------------------------------- launch ----------------------------------
extern "C" void kernel_launch(void* const* d_in, const int* in_sizes, int n_in,
                              void* d_out, int out_size)
{
    const float* query = (const float*)d_in[0];
    const float* refp  = (const float*)d_in[1];
    const float* v0    = (const float*)d_in[2];
    const float* v1    = (const float*)d_in[3];
    const float* v2    = (const float*)d_in[4];
    const float* Wv    = (const float*)d_in[5];
    const float* bv    = (const float*)d_in[6];
    const float* Wsmp  = (const float*)d_in[7];
    const float* bsmp  = (const float*)d_in[8];
    const float* Wa    = (const float*)d_in[9];
    const float* ba    = (const float*)d_in[10];
    const float* Wo    = (const float*)d_in[11];
    const float* bo    = (const float*)d_in[12];
    float* out = (float*)d_out;

    float *sa, *mid;
    cudaGetSymbolAddress((void**)&sa,  g_sa);
    cudaGetSymbolAddress((void**)&mid, g_mid);

    cudaFuncSetAttribute(gemm_fused1,
        cudaFuncAttributeMaxDynamicSharedMemorySize, SMEM_BYTES);
    cudaFuncSetAttribute(gemm_out,
        cudaFuncAttributeMaxDynamicSharedMemorySize, SMEM_BYTES);

    // 1) value projection + offs/attn GEMM, one launch
    gemm_fused1<<<FUSED_GRID, 256, SMEM_BYTES>>>(
        v0, v1, v2, Wv, bv, query, Wsmp, bsmp, Wa, ba, sa);
    // 2) sampling + softmax + aggregation
    sample_kernel<<<NR_, 256>>>(refp, mid);
    // 3) output projection: 157 x 4 tiles
    {
        dim3 grid((NR_ + 127) / 128, 4);
        gemm_out<<<grid, 256, SMEM_BYTES>>>(mid, Wo, bo, out);
    }
}

// round 16
// speedup vs baseline: 2.2342x; 1.1013x over previous
#include <cuda_runtime.h>
#include <cuda_bf16.h>
#include <cstdint>

// ---------------------------------------------------------------------------
// MSDeformableAttention — round 15: mma.sync bf16 3-product GEMMs, 128x128 CTA
// with 32x64 warp tiles (lower smem bytes/FLOP) AND 2 CTAs/SM (A-only register
// prefetch keeps regs <= 128). Fused value-proj + offs/attn launch kept.
//   B=2, NQ=10000, C=256, M=8, L=3, K=4, D=32; levels 100x100/50x50/25x25
// ---------------------------------------------------------------------------

#define B_    2
#define NQ_   10000
#define C_    256
#define M_    8
#define L_    3
#define KP_   4
#define D_    32
#define HW0   10000
#define HW1   2500
#define HW2   625
#define HWTOT 13125
#define NR_   (B_ * NQ_)     // 20000
#define SA_W  288            // 192 offsets + 96 attn logits per row

__device__ float g_proj[(size_t)B_ * HWTOT * C_];   // 26.9 MB, pixel-major
__device__ float g_sa  [(size_t)NR_ * SA_W];        // 23.0 MB
__device__ float g_mid [(size_t)NR_ * C_];          // 20.5 MB

// --------------------------- smem tile geometry ----------------------------
// Row stride 80 B: multiple of 16 (ldmatrix) and conflict-free across 8 rows.
#define TSTR       80
#define A_TILE     (128 * TSTR)        // 10240
#define OFF_AHI    0
#define OFF_ALO    (A_TILE)
#define OFF_BHI    (2 * A_TILE)
#define OFF_BLO    (3 * A_TILE)
#define BUF_BYTES  (4 * A_TILE)        // 40960
#define SMEM_BYTES (2 * BUF_BYTES)     // 81920 (double buffer)

// fused-launch block ranges: value-proj 208 x-tiles x 2 col, q-side 157 x 3
#define NVB        (208 * 2)           // 416
#define NQB        (157 * 3)           // 471
#define FUSED_GRID (NVB + NQB)

__device__ __forceinline__ uint32_t smem_u32(const void* p) {
    uint32_t a;
    asm("{ .reg .u64 t; cvta.to.shared.u64 t, %1; cvt.u32.u64 %0, t; }"
        : "=r"(a) : "l"(p));
    return a;
}
__device__ __forceinline__ void ldsm4(uint32_t r[4], uint32_t a) {
    asm volatile("ldmatrix.sync.aligned.m8n8.x4.shared.b16 {%0,%1,%2,%3}, [%4];"
                 : "=r"(r[0]), "=r"(r[1]), "=r"(r[2]), "=r"(r[3]) : "r"(a));
}
__device__ __forceinline__ void mma_bf(float* c, const uint32_t* a,
                                       uint32_t b0, uint32_t b1) {
    asm volatile(
        "mma.sync.aligned.m16n8k16.row.col.f32.bf16.bf16.f32 "
        "{%0,%1,%2,%3}, {%4,%5,%6,%7}, {%8,%9}, {%0,%1,%2,%3};"
        : "+f"(c[0]), "+f"(c[1]), "+f"(c[2]), "+f"(c[3])
        : "r"(a[0]), "r"(a[1]), "r"(a[2]), "r"(a[3]), "r"(b0), "r"(b1));
}
__device__ __forceinline__ uint32_t pk2(__nv_bfloat16 a, __nv_bfloat16 b) {
    __nv_bfloat162 t; t.x = a; t.y = b;
    return *reinterpret_cast<uint32_t*>(&t);
}
__device__ __forceinline__ void sts_split4(char* hiP, char* loP, float4 v) {
    __nv_bfloat16 hx = __float2bfloat16(v.x), hy = __float2bfloat16(v.y);
    __nv_bfloat16 hz = __float2bfloat16(v.z), hw = __float2bfloat16(v.w);
    __nv_bfloat16 lx = __float2bfloat16(v.x - __bfloat162float(hx));
    __nv_bfloat16 ly = __float2bfloat16(v.y - __bfloat162float(hy));
    __nv_bfloat16 lz = __float2bfloat16(v.z - __bfloat162float(hz));
    __nv_bfloat16 lw = __float2bfloat16(v.w - __bfloat162float(hw));
    *reinterpret_cast<uint2*>(hiP) = make_uint2(pk2(hx, hy), pk2(hz, hw));
    *reinterpret_cast<uint2*>(loP) = make_uint2(pk2(lx, ly), pk2(lz, lw));
}
__device__ __forceinline__ void sts_split1(char* hiP, char* loP, float f) {
    __nv_bfloat16 h = __float2bfloat16(f);
    __nv_bfloat16 l = __float2bfloat16(f - __bfloat162float(h));
    *reinterpret_cast<__nv_bfloat16*>(hiP) = h;
    *reinterpret_cast<__nv_bfloat16*>(loP) = l;
}

// -------------- per-chunk tensor compute: 128x128 CTA, 32x64 warp -----------
__device__ __forceinline__ void mma_compute128(char* buf, int warp_m,
                                               int warp_n, int lane,
                                               float acc[2][8][4]) {
    const uint32_t AhiB = smem_u32(buf + OFF_AHI);
    const uint32_t AloB = smem_u32(buf + OFF_ALO);
    const uint32_t BhiB = smem_u32(buf + OFF_BHI);
    const uint32_t BloB = smem_u32(buf + OFF_BLO);
    const uint32_t lrow = lane & 15;
    const uint32_t lkc  = (lane >> 4) * 16;   // k half-chunk byte offset
#pragma unroll
    for (int ks = 0; ks < 2; ks++) {
        const uint32_t kb = ks * 32 + lkc;
        uint32_t ahi[2][4], alo[2][4];
#pragma unroll
        for (int mt = 0; mt < 2; mt++) {
            const uint32_t off = (warp_m * 32 + mt * 16 + lrow) * TSTR + kb;
            ldsm4(ahi[mt], AhiB + off);
            ldsm4(alo[mt], AloB + off);
        }
#pragma unroll
        for (int ntp = 0; ntp < 4; ntp++) {
            const uint32_t off = (warp_n * 64 + ntp * 16 + lrow) * TSTR + kb;
            uint32_t bh[4], bl[4];
            ldsm4(bh, BhiB + off);
            ldsm4(bl, BloB + off);
#pragma unroll
            for (int mt = 0; mt < 2; mt++) {
                mma_bf(acc[mt][ntp * 2],     ahi[mt], bh[0], bh[2]);
                mma_bf(acc[mt][ntp * 2],     ahi[mt], bl[0], bl[2]);
                mma_bf(acc[mt][ntp * 2],     alo[mt], bh[0], bh[2]);
                mma_bf(acc[mt][ntp * 2 + 1], ahi[mt], bh[1], bh[3]);
                mma_bf(acc[mt][ntp * 2 + 1], ahi[mt], bl[1], bl[3]);
                mma_bf(acc[mt][ntp * 2 + 1], alo[mt], bh[1], bh[3]);
            }
        }
    }
}

// ---------------- row-major-A GEMM body: Y = X @ [W1;W2]^T + bias -----------
__device__ __forceinline__ void gemm_rowA_body(
    char* smem, int m0, int col0,
    const float* __restrict__ X, int Nrows,
    const float* __restrict__ W1, const float* __restrict__ b1, int O1,
    const float* __restrict__ W2, const float* __restrict__ b2, int Otot,
    float* __restrict__ Y, int ldy)
{
    const int tid = threadIdx.x, wid = tid >> 5, lane = tid & 31;
    const int warp_m = wid & 3, warp_n = wid >> 2;

    // loaders: 128 rows x 32 k, 4 float4 per thread (A and B use same map)
    const int lr = tid >> 1, lk = (tid & 1) * 16;
    const float* __restrict__ xrow =
        (m0 + lr < Nrows) ? X + (size_t)(m0 + lr) * C_ : nullptr;
    const int oG = col0 + lr;
    const float* __restrict__ wrow =
        (oG < O1) ? W1 + (size_t)oG * C_
                  : ((oG < Otot) ? W2 + (size_t)(oG - O1) * C_ : nullptr);
    const float4 z4 = make_float4(0.f, 0.f, 0.f, 0.f);

    // chunk 0: A + B straight into buf0
    {
        char* buf = smem;
        float4 aS[4];
#pragma unroll
        for (int i = 0; i < 4; i++)
            aS[i] = xrow ? *(const float4*)(xrow + lk + 4 * i) : z4;
#pragma unroll
        for (int i = 0; i < 4; i++) {
            const int kb = (lk + 4 * i) * 2;
            sts_split4(buf + OFF_AHI + lr * TSTR + kb,
                       buf + OFF_ALO + lr * TSTR + kb, aS[i]);
        }
#pragma unroll
        for (int i = 0; i < 4; i++) {
            const float4 bR = wrow ? *(const float4*)(wrow + lk + 4 * i) : z4;
            const int kb = (lk + 4 * i) * 2;
            sts_split4(buf + OFF_BHI + lr * TSTR + kb,
                       buf + OFF_BLO + lr * TSTR + kb, bR);
        }
    }
    __syncthreads();

    float acc[2][8][4];
#pragma unroll
    for (int mt = 0; mt < 2; mt++)
#pragma unroll
        for (int nt = 0; nt < 8; nt++)
#pragma unroll
            for (int i = 0; i < 4; i++) acc[mt][nt][i] = 0.f;

    float4 aS[4];
    for (int ch = 0; ch < 8; ch++) {
        if (ch < 7) {  // prefetch A only
            const int k0 = (ch + 1) * 32;
#pragma unroll
            for (int i = 0; i < 4; i++)
                aS[i] = xrow ? *(const float4*)(xrow + k0 + lk + 4 * i) : z4;
        }
        mma_compute128(smem + (ch & 1) * BUF_BYTES, warp_m, warp_n, lane, acc);
        if (ch < 7) {
            char* nb = smem + ((ch + 1) & 1) * BUF_BYTES;
#pragma unroll
            for (int i = 0; i < 4; i++) {
                const int kb = (lk + 4 * i) * 2;
                sts_split4(nb + OFF_AHI + lr * TSTR + kb,
                           nb + OFF_ALO + lr * TSTR + kb, aS[i]);
            }
            const int k0 = (ch + 1) * 32;
#pragma unroll
            for (int i = 0; i < 4; i++) {   // B: direct LDG->STS (L2-hot)
                const float4 bR =
                    wrow ? *(const float4*)(wrow + k0 + lk + 4 * i) : z4;
                const int kb = (lk + 4 * i) * 2;
                sts_split4(nb + OFF_BHI + lr * TSTR + kb,
                           nb + OFF_BLO + lr * TSTR + kb, bR);
            }
            __syncthreads();
        }
    }

#pragma unroll
    for (int mt = 0; mt < 2; mt++) {
        const int r0 = m0 + warp_m * 32 + mt * 16 + (lane >> 2);
#pragma unroll
        for (int nt = 0; nt < 8; nt++) {
            const int c = col0 + warp_n * 64 + nt * 8 + (lane & 3) * 2;
            if (c >= Otot) continue;
            const float bv0 = (c < O1) ? b1[c] : b2[c - O1];
            const float bv1 = (c + 1 < O1) ? b1[c + 1] : b2[c + 1 - O1];
            if (r0 < Nrows)
                *(float2*)(Y + (size_t)r0 * ldy + c) =
                    make_float2(acc[mt][nt][0] + bv0, acc[mt][nt][1] + bv1);
            if (r0 + 8 < Nrows)
                *(float2*)(Y + (size_t)(r0 + 8) * ldy + c) =
                    make_float2(acc[mt][nt][2] + bv0, acc[mt][nt][3] + bv1);
        }
    }
}

// ------------- value-projection GEMM body: A = V (C,HW) channel-major -------
__device__ __forceinline__ void gemm_v_body(
    char* smem, int vbid,
    const float* __restrict__ V0, const float* __restrict__ V1,
    const float* __restrict__ V2, const float* __restrict__ Wv,
    const float* __restrict__ bv)
{
    const int tid = threadIdx.x, wid = tid >> 5, lane = tid & 31;
    const int warp_m = wid & 3, warp_n = wid >> 2;
    const int xt = vbid >> 1;             // 0..207
    const int col0 = (vbid & 1) * 128;
    const int b  = xt / 104;
    const int tl = xt - b * 104;
    int p0, HW, loff;
    const float* A;
    if (tl < 79)      { p0 = tl * 128;        HW = HW0; loff = 0;         A = V0; }
    else if (tl < 99) { p0 = (tl - 79) * 128; HW = HW1; loff = HW0;       A = V1; }
    else              { p0 = (tl - 99) * 128; HW = HW2; loff = HW0 + HW1; A = V2; }
    A += (size_t)b * C_ * HW;

    // A loader: channel cL (0..31), 16 consecutive pixels at (tid&7)*16
    const int cL = tid >> 3;
    const int pb = (tid & 7) * 16;
    const bool vecOK = ((HW & 3) == 0) && (p0 + pb + 15 < HW);
    // B loader: 128 rows x 32 k
    const int lr = tid >> 1, lk = (tid & 1) * 16;
    const float* __restrict__ wrow = Wv + (size_t)(col0 + lr) * C_;

    // chunk 0
    {
        char* buf = smem;
        float aV[16];
        const float* src = A + (size_t)cL * HW + p0 + pb;
        if (vecOK) {
#pragma unroll
            for (int i = 0; i < 4; i++) {
                float4 v = *(const float4*)(src + 4 * i);
                aV[4*i] = v.x; aV[4*i+1] = v.y; aV[4*i+2] = v.z; aV[4*i+3] = v.w;
            }
        } else {
#pragma unroll
            for (int i = 0; i < 16; i++)
                aV[i] = (p0 + pb + i < HW) ? src[i] : 0.f;
        }
#pragma unroll
        for (int i = 0; i < 16; i++)
            sts_split1(buf + OFF_AHI + (pb + i) * TSTR + cL * 2,
                       buf + OFF_ALO + (pb + i) * TSTR + cL * 2, aV[i]);
#pragma unroll
        for (int i = 0; i < 4; i++) {
            const float4 bR = *(const float4*)(wrow + lk + 4 * i);
            const int kb = (lk + 4 * i) * 2;
            sts_split4(buf + OFF_BHI + lr * TSTR + kb,
                       buf + OFF_BLO + lr * TSTR + kb, bR);
        }
    }
    __syncthreads();

    float acc[2][8][4];
#pragma unroll
    for (int mt = 0; mt < 2; mt++)
#pragma unroll
        for (int nt = 0; nt < 8; nt++)
#pragma unroll
            for (int i = 0; i < 4; i++) acc[mt][nt][i] = 0.f;

    float aV[16];
    for (int ch = 0; ch < 8; ch++) {
        if (ch < 7) {  // prefetch A only
            const int k0 = (ch + 1) * 32;
            const float* src = A + (size_t)(k0 + cL) * HW + p0 + pb;
            if (vecOK) {
#pragma unroll
                for (int i = 0; i < 4; i++) {
                    float4 v = *(const float4*)(src + 4 * i);
                    aV[4*i] = v.x; aV[4*i+1] = v.y;
                    aV[4*i+2] = v.z; aV[4*i+3] = v.w;
                }
            } else {
#pragma unroll
                for (int i = 0; i < 16; i++)
                    aV[i] = (p0 + pb + i < HW) ? src[i] : 0.f;
            }
        }
        mma_compute128(smem + (ch & 1) * BUF_BYTES, warp_m, warp_n, lane, acc);
        if (ch < 7) {
            char* nb = smem + ((ch + 1) & 1) * BUF_BYTES;
#pragma unroll
            for (int i = 0; i < 16; i++)
                sts_split1(nb + OFF_AHI + (pb + i) * TSTR + cL * 2,
                           nb + OFF_ALO + (pb + i) * TSTR + cL * 2, aV[i]);
            const int k0 = (ch + 1) * 32;
#pragma unroll
            for (int i = 0; i < 4; i++) {   // B: direct LDG->STS
                const float4 bR = *(const float4*)(wrow + k0 + lk + 4 * i);
                const int kb = (lk + 4 * i) * 2;
                sts_split4(nb + OFF_BHI + lr * TSTR + kb,
                           nb + OFF_BLO + lr * TSTR + kb, bR);
            }
            __syncthreads();
        }
    }

    float* __restrict__ Y = g_proj + (size_t)(b * HWTOT + loff) * C_;
#pragma unroll
    for (int mt = 0; mt < 2; mt++) {
        const int r0 = warp_m * 32 + mt * 16 + (lane >> 2);
#pragma unroll
        for (int nt = 0; nt < 8; nt++) {
            const int c = col0 + warp_n * 64 + nt * 8 + (lane & 3) * 2;
            const float bv0 = bv[c], bv1 = bv[c + 1];
            if (p0 + r0 < HW)
                *(float2*)(Y + (size_t)(p0 + r0) * C_ + c) =
                    make_float2(acc[mt][nt][0] + bv0, acc[mt][nt][1] + bv1);
            if (p0 + r0 + 8 < HW)
                *(float2*)(Y + (size_t)(p0 + r0 + 8) * C_ + c) =
                    make_float2(acc[mt][nt][2] + bv0, acc[mt][nt][3] + bv1);
        }
    }
}

// ------------------ fused launch 1: value proj + offs/attn ------------------
__global__ __launch_bounds__(256, 2) void gemm_fused1(
    const float* __restrict__ V0, const float* __restrict__ V1,
    const float* __restrict__ V2, const float* __restrict__ Wv,
    const float* __restrict__ bv,
    const float* __restrict__ query,
    const float* __restrict__ Wsmp, const float* __restrict__ bsmp,
    const float* __restrict__ Wa,   const float* __restrict__ ba,
    float* __restrict__ sa)
{
    extern __shared__ char smem[];
    const int bid = blockIdx.x;
    if (bid < NVB) {
        gemm_v_body(smem, bid, V0, V1, V2, Wv, bv);
    } else {
        const int q = bid - NVB;
        const int xt = q / 3, yt = q - xt * 3;
        gemm_rowA_body(smem, xt * 128, yt * 128, query, NR_,
                       Wsmp, bsmp, 192, Wa, ba, SA_W, sa, SA_W);
    }
}

// --------------------------- output projection ------------------------------
__global__ __launch_bounds__(256, 2) void gemm_out(
    const float* __restrict__ X, const float* __restrict__ Wo,
    const float* __restrict__ bo, float* __restrict__ Y)
{
    extern __shared__ char smem[];
    gemm_rowA_body(smem, blockIdx.x * 128, blockIdx.y * 128, X, NR_,
                   Wo, bo, C_, Wo, bo, C_, Y, C_);
}

// ------------- bilinear sampling + aggregation, softmax fused ---------------
__global__ __launch_bounds__(256) void sample_kernel(
    const float* __restrict__ ref, float* __restrict__ mid)
{
    const int bq   = blockIdx.x;
    const int b    = bq / NQ_;
    const int warp = threadIdx.x >> 5;
    const int lane = threadIdx.x & 31;

    const float2 r2 = *(const float2*)(ref + 2 * bq);
    const float rx = r2.x, ry = r2.y;

    const float* __restrict__ row = g_sa + (size_t)bq * SA_W;
    const float* __restrict__ off_row = row + warp * 24;          // (L,K,2)

    float v = (lane < 12) ? row[192 + warp * 12 + lane] : -1e30f;
    float mx = v;
#pragma unroll
    for (int s = 16; s > 0; s >>= 1)
        mx = fmaxf(mx, __shfl_xor_sync(0xffffffffu, mx, s));
    float e = (lane < 12) ? __expf(v - mx) : 0.f;
    float ssum = e;
#pragma unroll
    for (int s = 16; s > 0; s >>= 1)
        ssum += __shfl_xor_sync(0xffffffffu, ssum, s);
    const float w = e * (1.f / ssum);

    const int Hs[3]    = {100, 50, 25};
    const int Ws_[3]   = {100, 50, 25};
    const int loffs[3] = {0, HW0, HW0 + HW1};

    float acc = 0.f;
#pragma unroll
    for (int l = 0; l < L_; l++) {
        const int Hh = Hs[l], Ww = Ws_[l];
        const float* projb =
            g_proj + ((size_t)b * HWTOT + loffs[l]) * C_ + warp * D_ + lane;
#pragma unroll
        for (int k = 0; k < KP_; k++) {
            const float ox = off_row[l * 8 + k * 2 + 0];
            const float oy = off_row[l * 8 + k * 2 + 1];
            const float aw = __shfl_sync(0xffffffffu, w, l * 4 + k);

            const float px = fmaf(rx, (float)Ww, ox) - 0.5f;
            const float py = fmaf(ry, (float)Hh, oy) - 0.5f;
            const float x0f = floorf(px), y0f = floorf(py);
            const int x0 = (int)x0f, y0 = (int)y0f;
            const float wx1 = px - x0f, wy1 = py - y0f;
            const float wx0 = 1.f - wx1, wy0 = 1.f - wy1;

            const bool vx0 = (x0 >= 0) && (x0 < Ww);
            const bool vx1 = (x0 + 1 >= 0) && (x0 + 1 < Ww);
            const bool vy0 = (y0 >= 0) && (y0 < Hh);
            const bool vy1 = (y0 + 1 >= 0) && (y0 + 1 < Hh);

            float s = 0.f;
            if (vy0) {
                const float* rowp = projb + (size_t)y0 * Ww * C_;
                if (vx0) s = fmaf(wx0 * wy0, rowp[(size_t)x0 * C_], s);
                if (vx1) s = fmaf(wx1 * wy0, rowp[(size_t)(x0 + 1) * C_], s);
            }
            if (vy1) {
                const float* rowp = projb + (size_t)(y0 + 1) * Ww * C_;
                if (vx0) s = fmaf(wx0 * wy1, rowp[(size_t)x0 * C_], s);
                if (vx1) s = fmaf(wx1 * wy1, rowp[(size_t)(x0 + 1) * C_], s);
            }
            acc = fmaf(aw, s, acc);
        }
    }
    mid[(size_t)bq * C_ + warp * D_ + lane] = acc;
}

// --------------------------------- launch ----------------------------------
extern "C" void kernel_launch(void* const* d_in, const int* in_sizes, int n_in,
                              void* d_out, int out_size)
{
    const float* query = (const float*)d_in[0];
    const float* refp  = (const float*)d_in[1];
    const float* v0    = (const float*)d_in[2];
    const float* v1    = (const float*)d_in[3];
    const float* v2    = (const float*)d_in[4];
    const float* Wv    = (const float*)d_in[5];
    const float* bv    = (const float*)d_in[6];
    const float* Wsmp  = (const float*)d_in[7];
    const float* bsmp  = (const float*)d_in[8];
    const float* Wa    = (const float*)d_in[9];
    const float* ba    = (const float*)d_in[10];
    const float* Wo    = (const float*)d_in[11];
    const float* bo    = (const float*)d_in[12];
    float* out = (float*)d_out;

    float *sa, *mid;
    cudaGetSymbolAddress((void**)&sa,  g_sa);
    cudaGetSymbolAddress((void**)&mid, g_mid);

    cudaFuncSetAttribute(gemm_fused1,
        cudaFuncAttributeMaxDynamicSharedMemorySize, SMEM_BYTES);
    cudaFuncSetAttribute(gemm_out,
        cudaFuncAttributeMaxDynamicSharedMemorySize, SMEM_BYTES);

    // 1) value projection + offs/attn GEMM, one launch
    gemm_fused1<<<FUSED_GRID, 256, SMEM_BYTES>>>(
        v0, v1, v2, Wv, bv, query, Wsmp, bsmp, Wa, ba, sa);
    // 2) sampling + softmax + aggregation
    sample_kernel<<<NR_, 256>>>(refp, mid);
    // 3) output projection: 157 x 2 tiles
    {
        dim3 grid((NR_ + 127) / 128, 2);
        gemm_out<<<grid, 256, SMEM_BYTES>>>(mid, Wo, bo, out);
    }
}